// round 8
// baseline (speedup 1.0000x reference)
#include <cuda_runtime.h>
#include <cuda_bf16.h>
#include <cstdint>

#define SEQ   2048
#define EMB   1024
#define NH    16
#define HD    64
#define BATCH 2
#define MTOT  (BATCH*SEQ)     // 4096
#define BHTOT (BATCH*NH)      // 32

// ---------------- scratch (static device globals; no allocations) ----------
__device__ __nv_bfloat16 g_Xhi[MTOT*EMB],  g_Xlo[MTOT*EMB];
__device__ __nv_bfloat16 g_Wqhi[EMB*EMB],  g_Wqlo[EMB*EMB];
__device__ __nv_bfloat16 g_Wkhi[EMB*EMB],  g_Wklo[EMB*EMB];
__device__ __nv_bfloat16 g_Wvhi[EMB*EMB],  g_Wvlo[EMB*EMB];
__device__ __nv_bfloat16 g_Wohi[EMB*EMB],  g_Wolo[EMB*EMB];
__device__ __nv_bfloat16 g_Hchi[MTOT*EMB], g_Hclo[MTOT*EMB];

// Attention operands (bf16 hi/lo). Q has x8 logit scale folded (exact).
__device__ __nv_bfloat16 g_Qhi[BHTOT*SEQ*HD], g_Qlo[BHTOT*SEQ*HD];
__device__ __nv_bfloat16 g_Khi[BHTOT*SEQ*HD], g_Klo[BHTOT*SEQ*HD];
// V stored transposed: [bh][d][seq]
__device__ __nv_bfloat16 g_Vthi[BHTOT*HD*SEQ], g_Vtlo[BHTOT*HD*SEQ];

// ---------------- PTX helpers (pre-Blackwell features; safe on sm_103) -----
__device__ __forceinline__ uint32_t smem_u32(const void* p) {
    uint32_t a;
    asm("{ .reg .u64 t; cvta.to.shared.u64 t, %1; cvt.u32.u64 %0, t; }"
        : "=r"(a) : "l"(p));
    return a;
}
__device__ __forceinline__ void cp16(uint32_t sdst, const void* gsrc) {
    asm volatile("cp.async.cg.shared.global [%0], [%1], 16;"
                 :: "r"(sdst), "l"(gsrc));
}
__device__ __forceinline__ void ldsm_x4(uint32_t a[4], uint32_t addr) {
    asm volatile("ldmatrix.sync.aligned.m8n8.x4.shared.b16 {%0,%1,%2,%3}, [%4];"
                 : "=r"(a[0]), "=r"(a[1]), "=r"(a[2]), "=r"(a[3]) : "r"(addr));
}
__device__ __forceinline__ void ldsm_x2(uint32_t a[2], uint32_t addr) {
    asm volatile("ldmatrix.sync.aligned.m8n8.x2.shared.b16 {%0,%1}, [%2];"
                 : "=r"(a[0]), "=r"(a[1]) : "r"(addr));
}
__device__ __forceinline__ void mma16816(float d[4], const uint32_t a[4],
                                         const uint32_t b[2]) {
    asm volatile(
        "mma.sync.aligned.m16n8k16.row.col.f32.bf16.bf16.f32 "
        "{%0,%1,%2,%3}, {%4,%5,%6,%7}, {%8,%9}, {%0,%1,%2,%3};"
        : "+f"(d[0]), "+f"(d[1]), "+f"(d[2]), "+f"(d[3])
        : "r"(a[0]), "r"(a[1]), "r"(a[2]), "r"(a[3]), "r"(b[0]), "r"(b[1]));
}
__device__ __forceinline__ uint32_t pack_bf16(float lo, float hi) {
    __nv_bfloat162 t = __halves2bfloat162(__float2bfloat16(lo),
                                          __float2bfloat16(hi));
    return *(uint32_t*)&t;
}

// ---------------- mma.sync GEMM v2: BM=128, BN=256, 3-stage ----------------
#define BK 32
#define NCHUNK (EMB/BK)       // 32
#define STRB 80               // smem row stride bytes (32 bf16 + 8 pad)
#define OFF_AHI 0
#define OFF_ALO 10240
#define OFF_BHI 20480
#define OFF_BLO 40960
#define STAGE_BYTES 61440
#define GEMM_SMEM_BYTES (3*STAGE_BYTES)   // 180 KB

__device__ __forceinline__ void gemm_load_chunk(
    uint32_t sb, int stage, int kc, int bm, int bn,
    const __nv_bfloat16* __restrict__ Ahi, const __nv_bfloat16* __restrict__ Alo,
    const __nv_bfloat16* __restrict__ Bhi, const __nv_bfloat16* __restrict__ Blo,
    int tid)
{
    const uint32_t st = sb + stage * STAGE_BYTES;
#pragma unroll
    for (int i = 0; i < 2; i++) {                 // A: 128 rows x 4 x 16B
        int idx = tid + i * 256;
        int row = idx >> 2, ch = idx & 3;
        uint32_t so = (uint32_t)(row * STRB + ch * 16);
        size_t ga = (size_t)(bm + row) * EMB + kc * BK + ch * 8;
        cp16(st + OFF_AHI + so, Ahi + ga);
        cp16(st + OFF_ALO + so, Alo + ga);
    }
#pragma unroll
    for (int i = 0; i < 4; i++) {                 // B: 256 rows x 4 x 16B
        int idx = tid + i * 256;
        int row = idx >> 2, ch = idx & 3;
        uint32_t so = (uint32_t)(row * STRB + ch * 16);
        size_t gb = (size_t)(bn + row) * EMB + kc * BK + ch * 8;
        cp16(st + OFF_BHI + so, Bhi + gb);
        cp16(st + OFF_BLO + so, Blo + gb);
    }
    asm volatile("cp.async.commit_group;" ::: "memory");
}

__device__ __forceinline__ void gemm_compute_stage(
    uint32_t sbase, int wm, int wn, int lane, float acc[4][8][4])
{
    const int ra = lane & 15;
    const uint32_t ka = (uint32_t)((lane >> 4) * 16);
    // B x4: lanes 0-15 -> rows n..n+7 (k halves 0,16B); lanes 16-31 -> rows n+8..n+15
    const int rb = ((lane >> 4) << 3) + (lane & 7);
    const uint32_t kb = (uint32_t)(((lane >> 3) & 1) * 16);
#pragma unroll
    for (int ks = 0; ks < 2; ks++) {
        uint32_t ah[4][4], al[4][4];
#pragma unroll
        for (int mi = 0; mi < 4; mi++) {
            uint32_t r = sbase + (uint32_t)((wm*64 + mi*16 + ra) * STRB) + ks*32 + ka;
            ldsm_x4(ah[mi], r + OFF_AHI);
            ldsm_x4(al[mi], r + OFF_ALO);
        }
#pragma unroll
        for (int nj = 0; nj < 4; nj++) {
            uint32_t bh[4], bl[4];
            uint32_t r = sbase + (uint32_t)((wn*64 + nj*16 + rb) * STRB) + ks*32 + kb;
            ldsm_x4(bh, r + OFF_BHI);
            ldsm_x4(bl, r + OFF_BLO);
#pragma unroll
            for (int mi = 0; mi < 4; mi++) {
                mma16816(acc[mi][2*nj],   ah[mi], bh);
                mma16816(acc[mi][2*nj],   ah[mi], bl);
                mma16816(acc[mi][2*nj],   al[mi], bh);
                mma16816(acc[mi][2*nj+1], ah[mi], bh + 2);
                mma16816(acc[mi][2*nj+1], ah[mi], bl + 2);
                mma16816(acc[mi][2*nj+1], al[mi], bh + 2);
            }
        }
    }
}

__device__ __forceinline__ void gemm_mainloop(
    uint32_t sb, int bm, int bn,
    const __nv_bfloat16* Ahi, const __nv_bfloat16* Alo,
    const __nv_bfloat16* Bhi, const __nv_bfloat16* Blo,
    int tid, int wm, int wn, int lane, float acc[4][8][4])
{
#pragma unroll
    for (int mi = 0; mi < 4; mi++)
#pragma unroll
        for (int ni = 0; ni < 8; ni++)
#pragma unroll
            for (int q = 0; q < 4; q++) acc[mi][ni][q] = 0.f;

    gemm_load_chunk(sb, 0, 0, bm, bn, Ahi, Alo, Bhi, Blo, tid);
    gemm_load_chunk(sb, 1, 1, bm, bn, Ahi, Alo, Bhi, Blo, tid);

    int stg = 0;
    for (int c = 0; c < NCHUNK; c++) {
        if (c == NCHUNK - 1)
            asm volatile("cp.async.wait_group 0;" ::: "memory");
        else
            asm volatile("cp.async.wait_group 1;" ::: "memory");
        __syncthreads();
        if (c + 2 < NCHUNK) {
            int ns = stg + 2; if (ns >= 3) ns -= 3;
            gemm_load_chunk(sb, ns, c + 2, bm, bn, Ahi, Alo, Bhi, Blo, tid);
        }
        gemm_compute_stage(sb + (uint32_t)(stg * STAGE_BYTES), wm, wn, lane, acc);
        if (++stg == 3) stg = 0;
    }
}

// ---------------- split kernel: fp32 -> (bf16 hi, bf16 lo) -----------------
__global__ __launch_bounds__(256) void split_kernel(
    const float* __restrict__ x,
    const float* __restrict__ Wq, const float* __restrict__ Wk,
    const float* __restrict__ Wv, const float* __restrict__ Wo)
{
    const float* src; __nv_bfloat16* hi; __nv_bfloat16* lo; int n4;
    switch (blockIdx.z) {
        case 0:  src = x;  hi = g_Xhi;  lo = g_Xlo;  n4 = MTOT*EMB/4; break;
        case 1:  src = Wq; hi = g_Wqhi; lo = g_Wqlo; n4 = EMB*EMB/4;  break;
        case 2:  src = Wk; hi = g_Wkhi; lo = g_Wklo; n4 = EMB*EMB/4;  break;
        case 3:  src = Wv; hi = g_Wvhi; lo = g_Wvlo; n4 = EMB*EMB/4;  break;
        default: src = Wo; hi = g_Wohi; lo = g_Wolo; n4 = EMB*EMB/4;  break;
    }
    for (int i = blockIdx.x * blockDim.x + threadIdx.x; i < n4;
         i += gridDim.x * blockDim.x) {
        float4 v = ((const float4*)src)[i];
        __nv_bfloat16 h0 = __float2bfloat16(v.x);
        __nv_bfloat16 h1 = __float2bfloat16(v.y);
        __nv_bfloat16 h2 = __float2bfloat16(v.z);
        __nv_bfloat16 h3 = __float2bfloat16(v.w);
        __nv_bfloat16 l0 = __float2bfloat16(v.x - __bfloat162float(h0));
        __nv_bfloat16 l1 = __float2bfloat16(v.y - __bfloat162float(h1));
        __nv_bfloat16 l2 = __float2bfloat16(v.z - __bfloat162float(h2));
        __nv_bfloat16 l3 = __float2bfloat16(v.w - __bfloat162float(h3));
        ((__nv_bfloat162*)hi)[2*i]   = __halves2bfloat162(h0, h1);
        ((__nv_bfloat162*)hi)[2*i+1] = __halves2bfloat162(h2, h3);
        ((__nv_bfloat162*)lo)[2*i]   = __halves2bfloat162(l0, l1);
        ((__nv_bfloat162*)lo)[2*i+1] = __halves2bfloat162(l2, l3);
    }
}

// ---------------- QKV projection: GEMM + bf16 hi/lo epilogue ----------------
__global__ __launch_bounds__(256) void qkv_gemm_tc(
    const float* __restrict__ bq, const float* __restrict__ bk,
    const float* __restrict__ bv)
{
    extern __shared__ char dsm[];
    uint32_t sb = smem_u32(dsm);
    const int tid = threadIdx.x, wid = tid >> 5, lane = tid & 31;
    const int wm = wid >> 2, wn = wid & 3;
    const int bm = blockIdx.x * 128, bn = blockIdx.y * 256;
    const int z = blockIdx.z;

    const __nv_bfloat16 *Bhi, *Blo; const float* bias;
    if (z == 0)      { Bhi = g_Wqhi; Blo = g_Wqlo; bias = bq; }
    else if (z == 1) { Bhi = g_Wkhi; Blo = g_Wklo; bias = bk; }
    else             { Bhi = g_Wvhi; Blo = g_Wvlo; bias = bv; }

    float acc[4][8][4];
    gemm_mainloop(sb, bm, bn, g_Xhi, g_Xlo, Bhi, Blo, tid, wm, wn, lane, acc);

    const int g = lane >> 2, tg = lane & 3;
    const float scl = (z == 0) ? 8.0f : 1.0f;
#pragma unroll
    for (int ni = 0; ni < 8; ni++) {
        const int c0 = bn + wn*64 + ni*8 + 2*tg;
        const float bx = bias[c0], by = bias[c0 + 1];
        const int h  = c0 >> 6;
        const int d0 = c0 & 63;
#pragma unroll
        for (int mi = 0; mi < 4; mi++) {
#pragma unroll
            for (int half = 0; half < 2; half++) {
                const int r = bm + wm*64 + mi*16 + g + half*8;
                const int b = r >> 11;
                const int n = r & (SEQ - 1);
                const int bh = (b << 4) + h;
                float v0 = (acc[mi][ni][half*2 + 0] + bx) * scl;
                float v1 = (acc[mi][ni][half*2 + 1] + by) * scl;
                __nv_bfloat16 h0 = __float2bfloat16(v0);
                __nv_bfloat16 h1 = __float2bfloat16(v1);
                __nv_bfloat16 l0 = __float2bfloat16(v0 - __bfloat162float(h0));
                __nv_bfloat16 l1 = __float2bfloat16(v1 - __bfloat162float(h1));
                if (z == 0) {
                    size_t o = ((size_t)bh * SEQ + n) * HD + d0;
                    *(__nv_bfloat162*)(g_Qhi + o) = __halves2bfloat162(h0, h1);
                    *(__nv_bfloat162*)(g_Qlo + o) = __halves2bfloat162(l0, l1);
                } else if (z == 1) {
                    size_t o = ((size_t)bh * SEQ + n) * HD + d0;
                    *(__nv_bfloat162*)(g_Khi + o) = __halves2bfloat162(h0, h1);
                    *(__nv_bfloat162*)(g_Klo + o) = __halves2bfloat162(l0, l1);
                } else {
                    size_t o0 = ((size_t)bh * HD + d0) * SEQ + n;
                    g_Vthi[o0]       = h0;  g_Vtlo[o0]       = l0;
                    g_Vthi[o0 + SEQ] = h1;  g_Vtlo[o0 + SEQ] = l1;
                }
            }
        }
    }
}

// ---------------- output projection ----------------------------------------
__global__ __launch_bounds__(256) void out_gemm_tc(
    const float* __restrict__ bo, float* __restrict__ outp)
{
    extern __shared__ char dsm[];
    uint32_t sb = smem_u32(dsm);
    const int tid = threadIdx.x, wid = tid >> 5, lane = tid & 31;
    const int wm = wid >> 2, wn = wid & 3;
    const int bm = blockIdx.x * 128, bn = blockIdx.y * 256;

    float acc[4][8][4];
    gemm_mainloop(sb, bm, bn, g_Hchi, g_Hclo, g_Wohi, g_Wolo,
                  tid, wm, wn, lane, acc);

    const int g = lane >> 2, tg = lane & 3;
#pragma unroll
    for (int ni = 0; ni < 8; ni++) {
        const int c0 = bn + wn*64 + ni*8 + 2*tg;
        const float bx = bo[c0], by = bo[c0 + 1];
#pragma unroll
        for (int mi = 0; mi < 4; mi++) {
#pragma unroll
            for (int half = 0; half < 2; half++) {
                const int r = bm + wm*64 + mi*16 + g + half*8;
                float* op = outp + (size_t)r * EMB + c0;
                float2 v = make_float2(acc[mi][ni][half*2 + 0] + bx,
                                       acc[mi][ni][half*2 + 1] + by);
                *(float2*)op = v;
            }
        }
    }
}

// ---------------- flash attention on HMMA, 3-stage KV pipeline --------------
#define ASTR 144                      // 64 bf16 + 8 pad = 144 B rows
#define AKHI 0
#define AKLO 9216
#define AVHI 18432
#define AVLO 27648
#define ASTG 36864                    // bytes per stage
#define ATT_SMEM (3*ASTG)             // 108 KB
#define NKT (SEQ/64)                  // 32

__device__ __forceinline__ void att_load_kv(uint32_t sb, int stage, int kt,
                                            int bh, int tid)
{
    const uint32_t st = sb + stage * ASTG;
    const __nv_bfloat16* kh = g_Khi  + ((size_t)bh*SEQ + kt*64) * HD;
    const __nv_bfloat16* kl = g_Klo  + ((size_t)bh*SEQ + kt*64) * HD;
    const __nv_bfloat16* vh = g_Vthi + (size_t)bh*HD*SEQ + kt*64;
    const __nv_bfloat16* vl = g_Vtlo + (size_t)bh*HD*SEQ + kt*64;
#pragma unroll
    for (int i = 0; i < 2; i++) {
        int idx = tid + i * 256;       // 512 chunks per matrix
        int row = idx >> 3, ch = idx & 7;
        uint32_t so = (uint32_t)(row * ASTR + ch * 16);
        cp16(st + AKHI + so, kh + (size_t)row * HD + ch * 8);
        cp16(st + AKLO + so, kl + (size_t)row * HD + ch * 8);
        cp16(st + AVHI + so, vh + (size_t)row * SEQ + ch * 8);
        cp16(st + AVLO + so, vl + (size_t)row * SEQ + ch * 8);
    }
    asm volatile("cp.async.commit_group;" ::: "memory");
}

__global__ __launch_bounds__(256, 2) void attn_mma()
{
    extern __shared__ char dsm[];
    uint32_t sb = smem_u32(dsm);
    const int tid = threadIdx.x, wid = tid >> 5, lane = tid & 31;
    const int g = lane >> 2, tg = lane & 3;
    const int bh = blockIdx.y, qblk = blockIdx.x;

    // ---- stage Q (hi at sb, lo at sb+18432), capture A-frags ----
    {
        const __nv_bfloat16* qh = g_Qhi + ((size_t)bh*SEQ + qblk*128) * HD;
        const __nv_bfloat16* ql = g_Qlo + ((size_t)bh*SEQ + qblk*128) * HD;
#pragma unroll
        for (int i = 0; i < 4; i++) {
            int idx = tid + i * 256;
            int row = idx >> 3, ch = idx & 7;
            uint32_t so = (uint32_t)(row * ASTR + ch * 16);
            cp16(sb + so,         qh + (size_t)row * HD + ch * 8);
            cp16(sb + 18432 + so, ql + (size_t)row * HD + ch * 8);
        }
        asm volatile("cp.async.commit_group;" ::: "memory");
        asm volatile("cp.async.wait_group 0;" ::: "memory");
        __syncthreads();
    }
    uint32_t qh[4][4], ql[4][4];
    {
        uint32_t qa = sb + (uint32_t)((wid*16 + (lane & 15)) * ASTR)
                         + (uint32_t)((lane >> 4) * 16);
#pragma unroll
        for (int ks = 0; ks < 4; ks++) {
            ldsm_x4(qh[ks], qa + ks*32);
            ldsm_x4(ql[ks], qa + 18432 + ks*32);
        }
    }
    __syncthreads();   // Q smem free for KV stages

    float oacc[8][4];
#pragma unroll
    for (int nf = 0; nf < 8; nf++)
#pragma unroll
        for (int q = 0; q < 4; q++) oacc[nf][q] = 0.f;
    float m_a = -1e30f, m_b = -1e30f, l_a = 0.f, l_b = 0.f;

    const int nb = lane & 7;
    const uint32_t kb = (uint32_t)(((lane >> 3) & 1) * 16);

    att_load_kv(sb, 0, 0, bh, tid);
    att_load_kv(sb, 1, 1, bh, tid);

    int stg = 0;
    for (int t = 0; t < NKT; t++) {
        if (t == NKT - 1)
            asm volatile("cp.async.wait_group 0;" ::: "memory");
        else
            asm volatile("cp.async.wait_group 1;" ::: "memory");
        __syncthreads();
        if (t + 2 < NKT) {
            int ns = stg + 2; if (ns >= 3) ns -= 3;
            att_load_kv(sb, ns, t + 2, bh, tid);
        }
        const uint32_t st = sb + (uint32_t)(stg * ASTG);
        if (++stg == 3) stg = 0;

        // ---- S = Q K^T (3-pass hi/lo, fp32 accum) ----
        float sacc[8][4];
#pragma unroll
        for (int nf = 0; nf < 8; nf++)
#pragma unroll
            for (int q = 0; q < 4; q++) sacc[nf][q] = 0.f;

#pragma unroll
        for (int ks = 0; ks < 4; ks++) {
#pragma unroll
            for (int nf = 0; nf < 8; nf++) {
                uint32_t ka = st + (uint32_t)((nf*8 + nb) * ASTR) + kb + ks*32;
                uint32_t bhh[2], bll[2];
                ldsm_x2(bhh, ka + AKHI);
                ldsm_x2(bll, ka + AKLO);
                mma16816(sacc[nf], qh[ks], bhh);
                mma16816(sacc[nf], ql[ks], bhh);
                mma16816(sacc[nf], qh[ks], bll);
            }
        }

        // ---- online softmax (rows g and g+8; reduce over tg lanes) ----
        float mx_a = sacc[0][0], mx_b = sacc[0][2];
#pragma unroll
        for (int nf = 0; nf < 8; nf++) {
            mx_a = fmaxf(mx_a, fmaxf(sacc[nf][0], sacc[nf][1]));
            mx_b = fmaxf(mx_b, fmaxf(sacc[nf][2], sacc[nf][3]));
        }
        mx_a = fmaxf(mx_a, __shfl_xor_sync(0xffffffffu, mx_a, 1));
        mx_a = fmaxf(mx_a, __shfl_xor_sync(0xffffffffu, mx_a, 2));
        mx_b = fmaxf(mx_b, __shfl_xor_sync(0xffffffffu, mx_b, 1));
        mx_b = fmaxf(mx_b, __shfl_xor_sync(0xffffffffu, mx_b, 2));

        float mna = fmaxf(m_a, mx_a), mnb = fmaxf(m_b, mx_b);
        float ala = __expf(m_a - mna), alb = __expf(m_b - mnb);
        m_a = mna; m_b = mnb;

        uint32_t phi[4][4], plo[4][4];
        float rs_a = 0.f, rs_b = 0.f;
#pragma unroll
        for (int ks = 0; ks < 4; ks++) {
#pragma unroll
            for (int jj = 0; jj < 2; jj++) {
                const int nf = 2*ks + jj;
                float p0 = __expf(sacc[nf][0] - m_a);
                float p1 = __expf(sacc[nf][1] - m_a);
                float p2 = __expf(sacc[nf][2] - m_b);
                float p3 = __expf(sacc[nf][3] - m_b);
                rs_a += p0 + p1; rs_b += p2 + p3;
                float h0f = __bfloat162float(__float2bfloat16(p0));
                float h1f = __bfloat162float(__float2bfloat16(p1));
                float h2f = __bfloat162float(__float2bfloat16(p2));
                float h3f = __bfloat162float(__float2bfloat16(p3));
                phi[ks][2*jj + 0] = pack_bf16(h0f, h1f);
                phi[ks][2*jj + 1] = pack_bf16(h2f, h3f);
                plo[ks][2*jj + 0] = pack_bf16(p0 - h0f, p1 - h1f);
                plo[ks][2*jj + 1] = pack_bf16(p2 - h2f, p3 - h3f);
            }
        }
        rs_a += __shfl_xor_sync(0xffffffffu, rs_a, 1);
        rs_a += __shfl_xor_sync(0xffffffffu, rs_a, 2);
        rs_b += __shfl_xor_sync(0xffffffffu, rs_b, 1);
        rs_b += __shfl_xor_sync(0xffffffffu, rs_b, 2);
        l_a = l_a * ala + rs_a;
        l_b = l_b * alb + rs_b;
#pragma unroll
        for (int nf = 0; nf < 8; nf++) {
            oacc[nf][0] *= ala; oacc[nf][1] *= ala;
            oacc[nf][2] *= alb; oacc[nf][3] *= alb;
        }

        // ---- O += P V (3-pass hi/lo) ----
#pragma unroll
        for (int ks = 0; ks < 4; ks++) {
#pragma unroll
            for (int nf = 0; nf < 8; nf++) {
                uint32_t va = st + (uint32_t)((nf*8 + nb) * ASTR) + kb + ks*32;
                uint32_t vhh[2], vll[2];
                ldsm_x2(vhh, va + AVHI);
                ldsm_x2(vll, va + AVLO);
                mma16816(oacc[nf], phi[ks], vhh);
                mma16816(oacc[nf], plo[ks], vhh);
                mma16816(oacc[nf], phi[ks], vll);
            }
        }
    }

    // ---- epilogue: normalize, emit Hc hi/lo bf16 ----
    const float iva = 1.0f / l_a, ivb = 1.0f / l_b;
    const int b = bh >> 4, h = bh & 15;
    const int tok_a = qblk*128 + wid*16 + g;
    const int tok_b = tok_a + 8;
#pragma unroll
    for (int nf = 0; nf < 8; nf++) {
        const int d = h*HD + nf*8 + 2*tg;
        float v0 = oacc[nf][0]*iva, v1 = oacc[nf][1]*iva;
        float v2 = oacc[nf][2]*ivb, v3 = oacc[nf][3]*ivb;
        size_t oa = ((size_t)(b*SEQ + tok_a))*EMB + d;
        size_t ob = ((size_t)(b*SEQ + tok_b))*EMB + d;
        __nv_bfloat16 h0 = __float2bfloat16(v0);
        __nv_bfloat16 h1 = __float2bfloat16(v1);
        __nv_bfloat16 h2 = __float2bfloat16(v2);
        __nv_bfloat16 h3 = __float2bfloat16(v3);
        *(__nv_bfloat162*)(g_Hchi + oa) = __halves2bfloat162(h0, h1);
        *(__nv_bfloat162*)(g_Hchi + ob) = __halves2bfloat162(h2, h3);
        *(__nv_bfloat162*)(g_Hclo + oa) = __halves2bfloat162(
            __float2bfloat16(v0 - __bfloat162float(h0)),
            __float2bfloat16(v1 - __bfloat162float(h1)));
        *(__nv_bfloat162*)(g_Hclo + ob) = __halves2bfloat162(
            __float2bfloat16(v2 - __bfloat162float(h2)),
            __float2bfloat16(v3 - __bfloat162float(h3)));
    }
}

// ---------------------------------------------------------------------------
extern "C" void kernel_launch(void* const* d_in, const int* in_sizes, int n_in,
                              void* d_out, int out_size)
{
    (void)in_sizes; (void)n_in; (void)out_size;
    const float* x  = (const float*)d_in[0];
    const float* Wq = (const float*)d_in[1];
    const float* bq = (const float*)d_in[2];
    const float* Wk = (const float*)d_in[3];
    const float* bk = (const float*)d_in[4];
    const float* Wv = (const float*)d_in[5];
    const float* bv = (const float*)d_in[6];
    const float* Wo = (const float*)d_in[7];
    const float* bo = (const float*)d_in[8];
    float* out = (float*)d_out;

    cudaFuncSetAttribute(qkv_gemm_tc,
                         cudaFuncAttributeMaxDynamicSharedMemorySize,
                         GEMM_SMEM_BYTES);
    cudaFuncSetAttribute(out_gemm_tc,
                         cudaFuncAttributeMaxDynamicSharedMemorySize,
                         GEMM_SMEM_BYTES);
    cudaFuncSetAttribute(attn_mma,
                         cudaFuncAttributeMaxDynamicSharedMemorySize,
                         ATT_SMEM);

    split_kernel<<<dim3(128, 1, 5), 256>>>(x, Wq, Wk, Wv, Wo);
    qkv_gemm_tc<<<dim3(MTOT/128, EMB/256, 3), 256, GEMM_SMEM_BYTES>>>(bq, bk, bv);
    attn_mma<<<dim3(SEQ/128, BHTOT), 256, ATT_SMEM>>>();
    out_gemm_tc<<<dim3(MTOT/128, EMB/256), 256, GEMM_SMEM_BYTES>>>(bo, out);
}

// round 10
// speedup vs baseline: 1.5615x; 1.5615x over previous
#include <cuda_runtime.h>
#include <cuda_bf16.h>
#include <cstdint>

#define SEQ   2048
#define EMB   1024
#define NH    16
#define HD    64
#define BATCH 2
#define MTOT  (BATCH*SEQ)     // 4096
#define BHTOT (BATCH*NH)      // 32

// ---------------- scratch (static device globals; no allocations) ----------
__device__ __nv_bfloat16 g_Xhi[MTOT*EMB],  g_Xlo[MTOT*EMB];
__device__ __nv_bfloat16 g_Wqhi[EMB*EMB],  g_Wqlo[EMB*EMB];
__device__ __nv_bfloat16 g_Wkhi[EMB*EMB],  g_Wklo[EMB*EMB];
__device__ __nv_bfloat16 g_Wvhi[EMB*EMB],  g_Wvlo[EMB*EMB];
__device__ __nv_bfloat16 g_Wohi[EMB*EMB],  g_Wolo[EMB*EMB];
__device__ __nv_bfloat16 g_Hchi[MTOT*EMB], g_Hclo[MTOT*EMB];

// Attention operands (bf16 hi/lo). Q has x8 logit scale folded (exact).
__device__ __nv_bfloat16 g_Qhi[BHTOT*SEQ*HD], g_Qlo[BHTOT*SEQ*HD];
__device__ __nv_bfloat16 g_Khi[BHTOT*SEQ*HD], g_Klo[BHTOT*SEQ*HD];
// V stored transposed: [bh][d][seq]
__device__ __nv_bfloat16 g_Vthi[BHTOT*HD*SEQ], g_Vtlo[BHTOT*HD*SEQ];

// ---------------- PTX helpers (pre-Blackwell features; safe on sm_103) -----
__device__ __forceinline__ uint32_t smem_u32(const void* p) {
    uint32_t a;
    asm("{ .reg .u64 t; cvta.to.shared.u64 t, %1; cvt.u32.u64 %0, t; }"
        : "=r"(a) : "l"(p));
    return a;
}
__device__ __forceinline__ void cp16(uint32_t sdst, const void* gsrc) {
    asm volatile("cp.async.cg.shared.global [%0], [%1], 16;"
                 :: "r"(sdst), "l"(gsrc));
}
__device__ __forceinline__ void ldsm_x4(uint32_t a[4], uint32_t addr) {
    asm volatile("ldmatrix.sync.aligned.m8n8.x4.shared.b16 {%0,%1,%2,%3}, [%4];"
                 : "=r"(a[0]), "=r"(a[1]), "=r"(a[2]), "=r"(a[3]) : "r"(addr));
}
__device__ __forceinline__ void ldsm_x2(uint32_t a[2], uint32_t addr) {
    asm volatile("ldmatrix.sync.aligned.m8n8.x2.shared.b16 {%0,%1}, [%2];"
                 : "=r"(a[0]), "=r"(a[1]) : "r"(addr));
}
__device__ __forceinline__ void mma16816(float d[4], const uint32_t a[4],
                                         const uint32_t b[2]) {
    asm volatile(
        "mma.sync.aligned.m16n8k16.row.col.f32.bf16.bf16.f32 "
        "{%0,%1,%2,%3}, {%4,%5,%6,%7}, {%8,%9}, {%0,%1,%2,%3};"
        : "+f"(d[0]), "+f"(d[1]), "+f"(d[2]), "+f"(d[3])
        : "r"(a[0]), "r"(a[1]), "r"(a[2]), "r"(a[3]), "r"(b[0]), "r"(b[1]));
}
__device__ __forceinline__ uint32_t pack_bf16(float lo, float hi) {
    __nv_bfloat162 t = __halves2bfloat162(__float2bfloat16(lo),
                                          __float2bfloat16(hi));
    return *(uint32_t*)&t;
}

// ---------------- mma.sync GEMM (R7 config: 128x128, 2-stage, 80KB) --------
#define BK 32
#define NCHUNK (EMB/BK)       // 32
#define STRB 80               // smem row stride bytes (32 bf16 + 8 pad)
#define OFF_AHI 0
#define OFF_ALO 10240
#define OFF_BHI 20480
#define OFF_BLO 30720
#define STAGE_BYTES 40960
#define GEMM_SMEM_BYTES (2*STAGE_BYTES)   // 80 KB

__device__ __forceinline__ void gemm_load_chunk(
    uint32_t sb, int stage, int kc, int bm, int bn,
    const __nv_bfloat16* __restrict__ Ahi, const __nv_bfloat16* __restrict__ Alo,
    const __nv_bfloat16* __restrict__ Bhi, const __nv_bfloat16* __restrict__ Blo,
    int tid)
{
    const uint32_t st = sb + stage * STAGE_BYTES;
#pragma unroll
    for (int i = 0; i < 2; i++) {
        int idx = tid + i * 256;
        int row = idx >> 2, ch = idx & 3;
        uint32_t so = (uint32_t)(row * STRB + ch * 16);
        size_t ga = (size_t)(bm + row) * EMB + kc * BK + ch * 8;
        size_t gb = (size_t)(bn + row) * EMB + kc * BK + ch * 8;
        cp16(st + OFF_AHI + so, Ahi + ga);
        cp16(st + OFF_ALO + so, Alo + ga);
        cp16(st + OFF_BHI + so, Bhi + gb);
        cp16(st + OFF_BLO + so, Blo + gb);
    }
    asm volatile("cp.async.commit_group;" ::: "memory");
}

// MMA issue reordered pass-major: consecutive MMAs always hit different
// accumulators (16 independent tiles between same-acc reuses).
__device__ __forceinline__ void gemm_compute_stage(
    uint32_t sbase, int wm, int wn, int lane, float acc[4][4][4])
{
    const int ra      = lane & 15;
    const uint32_t ka = (uint32_t)((lane >> 4) * 16);
    const int nb      = lane & 7;
    const uint32_t kb = (uint32_t)(((lane >> 3) & 1) * 16);
#pragma unroll
    for (int ks = 0; ks < 2; ks++) {
        uint32_t ah[4][4], al[4][4], bh[4][2], bl[4][2];
#pragma unroll
        for (int mi = 0; mi < 4; mi++) {
            uint32_t r = sbase + (uint32_t)((wm*64 + mi*16 + ra) * STRB) + ks*32 + ka;
            ldsm_x4(ah[mi], r + OFF_AHI);
            ldsm_x4(al[mi], r + OFF_ALO);
        }
#pragma unroll
        for (int ni = 0; ni < 4; ni++) {
            uint32_t r = sbase + (uint32_t)((wn*32 + ni*8 + nb) * STRB) + ks*32 + kb;
            ldsm_x2(bh[ni], r + OFF_BHI);
            ldsm_x2(bl[ni], r + OFF_BLO);
        }
        // pass 0: Ahi * Bhi
#pragma unroll
        for (int mi = 0; mi < 4; mi++)
#pragma unroll
            for (int ni = 0; ni < 4; ni++)
                mma16816(acc[mi][ni], ah[mi], bh[ni]);
        // pass 1: Ahi * Blo
#pragma unroll
        for (int mi = 0; mi < 4; mi++)
#pragma unroll
            for (int ni = 0; ni < 4; ni++)
                mma16816(acc[mi][ni], ah[mi], bl[ni]);
        // pass 2: Alo * Bhi
#pragma unroll
        for (int mi = 0; mi < 4; mi++)
#pragma unroll
            for (int ni = 0; ni < 4; ni++)
                mma16816(acc[mi][ni], al[mi], bh[ni]);
    }
}

__device__ __forceinline__ void gemm_mainloop(
    uint32_t sb, int bm, int bn,
    const __nv_bfloat16* Ahi, const __nv_bfloat16* Alo,
    const __nv_bfloat16* Bhi, const __nv_bfloat16* Blo,
    int tid, int wm, int wn, int lane, float acc[4][4][4])
{
#pragma unroll
    for (int mi = 0; mi < 4; mi++)
#pragma unroll
        for (int ni = 0; ni < 4; ni++)
#pragma unroll
            for (int q = 0; q < 4; q++) acc[mi][ni][q] = 0.f;

    gemm_load_chunk(sb, 0, 0, bm, bn, Ahi, Alo, Bhi, Blo, tid);

    for (int c = 0; c < NCHUNK; c++) {
        if (c + 1 < NCHUNK) {
            gemm_load_chunk(sb, (c + 1) & 1, c + 1, bm, bn, Ahi, Alo, Bhi, Blo, tid);
            asm volatile("cp.async.wait_group 1;" ::: "memory");
        } else {
            asm volatile("cp.async.wait_group 0;" ::: "memory");
        }
        __syncthreads();
        gemm_compute_stage(sb + (uint32_t)((c & 1) * STAGE_BYTES), wm, wn, lane, acc);
        __syncthreads();
    }
}

// ---------------- split kernel: fp32 -> (bf16 hi, bf16 lo) -----------------
__global__ __launch_bounds__(256) void split_kernel(
    const float* __restrict__ x,
    const float* __restrict__ Wq, const float* __restrict__ Wk,
    const float* __restrict__ Wv, const float* __restrict__ Wo)
{
    const float* src; __nv_bfloat16* hi; __nv_bfloat16* lo; int n4;
    switch (blockIdx.z) {
        case 0:  src = x;  hi = g_Xhi;  lo = g_Xlo;  n4 = MTOT*EMB/4; break;
        case 1:  src = Wq; hi = g_Wqhi; lo = g_Wqlo; n4 = EMB*EMB/4;  break;
        case 2:  src = Wk; hi = g_Wkhi; lo = g_Wklo; n4 = EMB*EMB/4;  break;
        case 3:  src = Wv; hi = g_Wvhi; lo = g_Wvlo; n4 = EMB*EMB/4;  break;
        default: src = Wo; hi = g_Wohi; lo = g_Wolo; n4 = EMB*EMB/4;  break;
    }
    for (int i = blockIdx.x * blockDim.x + threadIdx.x; i < n4;
         i += gridDim.x * blockDim.x) {
        float4 v = ((const float4*)src)[i];
        __nv_bfloat16 h0 = __float2bfloat16(v.x);
        __nv_bfloat16 h1 = __float2bfloat16(v.y);
        __nv_bfloat16 h2 = __float2bfloat16(v.z);
        __nv_bfloat16 h3 = __float2bfloat16(v.w);
        __nv_bfloat16 l0 = __float2bfloat16(v.x - __bfloat162float(h0));
        __nv_bfloat16 l1 = __float2bfloat16(v.y - __bfloat162float(h1));
        __nv_bfloat16 l2 = __float2bfloat16(v.z - __bfloat162float(h2));
        __nv_bfloat16 l3 = __float2bfloat16(v.w - __bfloat162float(h3));
        ((__nv_bfloat162*)hi)[2*i]   = __halves2bfloat162(h0, h1);
        ((__nv_bfloat162*)hi)[2*i+1] = __halves2bfloat162(h2, h3);
        ((__nv_bfloat162*)lo)[2*i]   = __halves2bfloat162(l0, l1);
        ((__nv_bfloat162*)lo)[2*i+1] = __halves2bfloat162(l2, l3);
    }
}

// ---------------- QKV projection: GEMM + bf16 hi/lo epilogue ----------------
__global__ __launch_bounds__(256) void qkv_gemm_tc(
    const float* __restrict__ bq, const float* __restrict__ bk,
    const float* __restrict__ bv)
{
    extern __shared__ char dsm[];
    uint32_t sb = smem_u32(dsm);
    const int tid = threadIdx.x, wid = tid >> 5, lane = tid & 31;
    const int wm = wid >> 2, wn = wid & 3;
    const int bm = blockIdx.x * 128, bn = blockIdx.y * 128;
    const int z = blockIdx.z;

    const __nv_bfloat16 *Bhi, *Blo; const float* bias;
    if (z == 0)      { Bhi = g_Wqhi; Blo = g_Wqlo; bias = bq; }
    else if (z == 1) { Bhi = g_Wkhi; Blo = g_Wklo; bias = bk; }
    else             { Bhi = g_Wvhi; Blo = g_Wvlo; bias = bv; }

    float acc[4][4][4];
    gemm_mainloop(sb, bm, bn, g_Xhi, g_Xlo, Bhi, Blo, tid, wm, wn, lane, acc);

    const int g = lane >> 2, tg = lane & 3;
    const float scl = (z == 0) ? 8.0f : 1.0f;
#pragma unroll
    for (int ni = 0; ni < 4; ni++) {
        const int c0 = bn + wn*32 + ni*8 + 2*tg;
        const float bx = bias[c0], by = bias[c0 + 1];
        const int h  = c0 >> 6;
        const int d0 = c0 & 63;
#pragma unroll
        for (int mi = 0; mi < 4; mi++) {
#pragma unroll
            for (int half = 0; half < 2; half++) {
                const int r = bm + wm*64 + mi*16 + g + half*8;
                const int b = r >> 11;
                const int n = r & (SEQ - 1);
                const int bh = (b << 4) + h;
                float v0 = (acc[mi][ni][half*2 + 0] + bx) * scl;
                float v1 = (acc[mi][ni][half*2 + 1] + by) * scl;
                __nv_bfloat16 h0 = __float2bfloat16(v0);
                __nv_bfloat16 h1 = __float2bfloat16(v1);
                __nv_bfloat16 l0 = __float2bfloat16(v0 - __bfloat162float(h0));
                __nv_bfloat16 l1 = __float2bfloat16(v1 - __bfloat162float(h1));
                if (z == 0) {
                    size_t o = ((size_t)bh * SEQ + n) * HD + d0;
                    *(__nv_bfloat162*)(g_Qhi + o) = __halves2bfloat162(h0, h1);
                    *(__nv_bfloat162*)(g_Qlo + o) = __halves2bfloat162(l0, l1);
                } else if (z == 1) {
                    size_t o = ((size_t)bh * SEQ + n) * HD + d0;
                    *(__nv_bfloat162*)(g_Khi + o) = __halves2bfloat162(h0, h1);
                    *(__nv_bfloat162*)(g_Klo + o) = __halves2bfloat162(l0, l1);
                } else {
                    // V transposed: [bh][d][seq]
                    size_t o0 = ((size_t)bh * HD + d0) * SEQ + n;
                    g_Vthi[o0]       = h0;  g_Vtlo[o0]       = l0;
                    g_Vthi[o0 + SEQ] = h1;  g_Vtlo[o0 + SEQ] = l1;
                }
            }
        }
    }
}

// ---------------- output projection -----------------------------------------
__global__ __launch_bounds__(256) void out_gemm_tc(
    const float* __restrict__ bo, float* __restrict__ outp)
{
    extern __shared__ char dsm[];
    uint32_t sb = smem_u32(dsm);
    const int tid = threadIdx.x, wid = tid >> 5, lane = tid & 31;
    const int wm = wid >> 2, wn = wid & 3;
    const int bm = blockIdx.x * 128, bn = blockIdx.y * 128;

    float acc[4][4][4];
    gemm_mainloop(sb, bm, bn, g_Hchi, g_Hclo, g_Wohi, g_Wolo,
                  tid, wm, wn, lane, acc);

    const int g = lane >> 2, tg = lane & 3;
#pragma unroll
    for (int ni = 0; ni < 4; ni++) {
        const int c0 = bn + wn*32 + ni*8 + 2*tg;
        const float bx = bo[c0], by = bo[c0 + 1];
#pragma unroll
        for (int mi = 0; mi < 4; mi++) {
#pragma unroll
            for (int half = 0; half < 2; half++) {
                const int r = bm + wm*64 + mi*16 + g + half*8;
                float* op = outp + (size_t)r * EMB + c0;
                float2 v = make_float2(acc[mi][ni][half*2 + 0] + bx,
                                       acc[mi][ni][half*2 + 1] + by);
                *(float2*)op = v;
            }
        }
    }
}

// ---------------- flash attention on HMMA (R7 config, reordered MMAs) -------
#define ASTR 144                      // 64 bf16 + 8 pad = 144 B rows
#define AKHI 0
#define AKLO 9216
#define AVHI 18432
#define AVLO 27648
#define ASTG 36864                    // bytes per stage
#define ATT_SMEM (2*ASTG)             // 72 KB
#define NKT (SEQ/64)                  // 32

__device__ __forceinline__ void att_load_kv(uint32_t sb, int stage, int kt,
                                            int bh, int tid)
{
    const uint32_t st = sb + stage * ASTG;
    const __nv_bfloat16* kh = g_Khi  + ((size_t)bh*SEQ + kt*64) * HD;
    const __nv_bfloat16* kl = g_Klo  + ((size_t)bh*SEQ + kt*64) * HD;
    const __nv_bfloat16* vh = g_Vthi + (size_t)bh*HD*SEQ + kt*64;
    const __nv_bfloat16* vl = g_Vtlo + (size_t)bh*HD*SEQ + kt*64;
#pragma unroll
    for (int i = 0; i < 2; i++) {
        int idx = tid + i * 256;
        int row = idx >> 3, ch = idx & 7;
        uint32_t so = (uint32_t)(row * ASTR + ch * 16);
        cp16(st + AKHI + so, kh + (size_t)row * HD + ch * 8);
        cp16(st + AKLO + so, kl + (size_t)row * HD + ch * 8);
        cp16(st + AVHI + so, vh + (size_t)row * SEQ + ch * 8);
        cp16(st + AVLO + so, vl + (size_t)row * SEQ + ch * 8);
    }
    asm volatile("cp.async.commit_group;" ::: "memory");
}

__global__ __launch_bounds__(256, 2) void attn_mma()
{
    extern __shared__ char dsm[];
    uint32_t sb = smem_u32(dsm);
    const int tid = threadIdx.x, wid = tid >> 5, lane = tid & 31;
    const int g = lane >> 2, tg = lane & 3;
    const int bh = blockIdx.y, qblk = blockIdx.x;

    // ---- stage Q (hi at sb, lo at sb+18432), capture A-frags ----
    {
        const __nv_bfloat16* qh = g_Qhi + ((size_t)bh*SEQ + qblk*128) * HD;
        const __nv_bfloat16* ql = g_Qlo + ((size_t)bh*SEQ + qblk*128) * HD;
#pragma unroll
        for (int i = 0; i < 4; i++) {
            int idx = tid + i * 256;
            int row = idx >> 3, ch = idx & 7;
            uint32_t so = (uint32_t)(row * ASTR + ch * 16);
            cp16(sb + so,         qh + (size_t)row * HD + ch * 8);
            cp16(sb + 18432 + so, ql + (size_t)row * HD + ch * 8);
        }
        asm volatile("cp.async.commit_group;" ::: "memory");
        asm volatile("cp.async.wait_group 0;" ::: "memory");
        __syncthreads();
    }
    uint32_t qh[4][4], ql[4][4];
    {
        uint32_t qa = sb + (uint32_t)((wid*16 + (lane & 15)) * ASTR)
                         + (uint32_t)((lane >> 4) * 16);
#pragma unroll
        for (int ks = 0; ks < 4; ks++) {
            ldsm_x4(qh[ks], qa + ks*32);
            ldsm_x4(ql[ks], qa + 18432 + ks*32);
        }
    }
    __syncthreads();   // Q smem free for KV stages

    float oacc[8][4];
#pragma unroll
    for (int nf = 0; nf < 8; nf++)
#pragma unroll
        for (int q = 0; q < 4; q++) oacc[nf][q] = 0.f;
    float m_a = -1e30f, m_b = -1e30f, l_a = 0.f, l_b = 0.f;

    const int nb = lane & 7;
    const uint32_t kb = (uint32_t)(((lane >> 3) & 1) * 16);

    att_load_kv(sb, 0, 0, bh, tid);

    for (int t = 0; t < NKT; t++) {
        if (t + 1 < NKT) {
            att_load_kv(sb, (t + 1) & 1, t + 1, bh, tid);
            asm volatile("cp.async.wait_group 1;" ::: "memory");
        } else {
            asm volatile("cp.async.wait_group 0;" ::: "memory");
        }
        __syncthreads();
        const uint32_t st = sb + (uint32_t)((t & 1) * ASTG);

        // ---- S = Q K^T (3-pass hi/lo; nf-pairs interleaved, dep distance 2) ----
        float sacc[8][4];
#pragma unroll
        for (int nf = 0; nf < 8; nf++)
#pragma unroll
            for (int q = 0; q < 4; q++) sacc[nf][q] = 0.f;

#pragma unroll
        for (int ks = 0; ks < 4; ks++) {
#pragma unroll
            for (int np = 0; np < 4; np++) {
                const int nf0 = 2*np, nf1 = 2*np + 1;
                uint32_t ka0 = st + (uint32_t)((nf0*8 + nb) * ASTR) + kb + ks*32;
                uint32_t ka1 = st + (uint32_t)((nf1*8 + nb) * ASTR) + kb + ks*32;
                uint32_t bh0[2], bl0[2], bh1[2], bl1[2];
                ldsm_x2(bh0, ka0 + AKHI);
                ldsm_x2(bh1, ka1 + AKHI);
                ldsm_x2(bl0, ka0 + AKLO);
                ldsm_x2(bl1, ka1 + AKLO);
                mma16816(sacc[nf0], qh[ks], bh0);
                mma16816(sacc[nf1], qh[ks], bh1);
                mma16816(sacc[nf0], ql[ks], bh0);
                mma16816(sacc[nf1], ql[ks], bh1);
                mma16816(sacc[nf0], qh[ks], bl0);
                mma16816(sacc[nf1], qh[ks], bl1);
            }
        }

        // ---- online softmax (rows g and g+8; reduce over tg lanes) ----
        float mx_a = sacc[0][0], mx_b = sacc[0][2];
#pragma unroll
        for (int nf = 0; nf < 8; nf++) {
            mx_a = fmaxf(mx_a, fmaxf(sacc[nf][0], sacc[nf][1]));
            mx_b = fmaxf(mx_b, fmaxf(sacc[nf][2], sacc[nf][3]));
        }
        mx_a = fmaxf(mx_a, __shfl_xor_sync(0xffffffffu, mx_a, 1));
        mx_a = fmaxf(mx_a, __shfl_xor_sync(0xffffffffu, mx_a, 2));
        mx_b = fmaxf(mx_b, __shfl_xor_sync(0xffffffffu, mx_b, 1));
        mx_b = fmaxf(mx_b, __shfl_xor_sync(0xffffffffu, mx_b, 2));

        float mna = fmaxf(m_a, mx_a), mnb = fmaxf(m_b, mx_b);
        float ala = __expf(m_a - mna), alb = __expf(m_b - mnb);
        m_a = mna; m_b = mnb;

        uint32_t phi[4][4], plo[4][4];
        float rs_a = 0.f, rs_b = 0.f;
#pragma unroll
        for (int ks = 0; ks < 4; ks++) {
#pragma unroll
            for (int jj = 0; jj < 2; jj++) {
                const int nf = 2*ks + jj;
                float p0 = __expf(sacc[nf][0] - m_a);
                float p1 = __expf(sacc[nf][1] - m_a);
                float p2 = __expf(sacc[nf][2] - m_b);
                float p3 = __expf(sacc[nf][3] - m_b);
                rs_a += p0 + p1; rs_b += p2 + p3;
                float h0f = __bfloat162float(__float2bfloat16(p0));
                float h1f = __bfloat162float(__float2bfloat16(p1));
                float h2f = __bfloat162float(__float2bfloat16(p2));
                float h3f = __bfloat162float(__float2bfloat16(p3));
                phi[ks][2*jj + 0] = pack_bf16(h0f, h1f);
                phi[ks][2*jj + 1] = pack_bf16(h2f, h3f);
                plo[ks][2*jj + 0] = pack_bf16(p0 - h0f, p1 - h1f);
                plo[ks][2*jj + 1] = pack_bf16(p2 - h2f, p3 - h3f);
            }
        }
        rs_a += __shfl_xor_sync(0xffffffffu, rs_a, 1);
        rs_a += __shfl_xor_sync(0xffffffffu, rs_a, 2);
        rs_b += __shfl_xor_sync(0xffffffffu, rs_b, 1);
        rs_b += __shfl_xor_sync(0xffffffffu, rs_b, 2);
        l_a = l_a * ala + rs_a;
        l_b = l_b * alb + rs_b;
#pragma unroll
        for (int nf = 0; nf < 8; nf++) {
            oacc[nf][0] *= ala; oacc[nf][1] *= ala;
            oacc[nf][2] *= alb; oacc[nf][3] *= alb;
        }

        // ---- O += P V (3-pass hi/lo; nf-pairs interleaved) ----
#pragma unroll
        for (int ks = 0; ks < 4; ks++) {
#pragma unroll
            for (int np = 0; np < 4; np++) {
                const int nf0 = 2*np, nf1 = 2*np + 1;
                uint32_t va0 = st + (uint32_t)((nf0*8 + nb) * ASTR) + kb + ks*32;
                uint32_t va1 = st + (uint32_t)((nf1*8 + nb) * ASTR) + kb + ks*32;
                uint32_t vh0[2], vl0[2], vh1[2], vl1[2];
                ldsm_x2(vh0, va0 + AVHI);
                ldsm_x2(vh1, va1 + AVHI);
                ldsm_x2(vl0, va0 + AVLO);
                ldsm_x2(vl1, va1 + AVLO);
                mma16816(oacc[nf0], phi[ks], vh0);
                mma16816(oacc[nf1], phi[ks], vh1);
                mma16816(oacc[nf0], plo[ks], vh0);
                mma16816(oacc[nf1], plo[ks], vh1);
                mma16816(oacc[nf0], phi[ks], vl0);
                mma16816(oacc[nf1], phi[ks], vl1);
            }
        }
        __syncthreads();
    }

    // ---- epilogue: normalize, emit Hc hi/lo bf16 ----
    const float iva = 1.0f / l_a, ivb = 1.0f / l_b;
    const int b = bh >> 4, h = bh & 15;
    const int tok_a = qblk*128 + wid*16 + g;
    const int tok_b = tok_a + 8;
#pragma unroll
    for (int nf = 0; nf < 8; nf++) {
        const int d = h*HD + nf*8 + 2*tg;
        float v0 = oacc[nf][0]*iva, v1 = oacc[nf][1]*iva;
        float v2 = oacc[nf][2]*ivb, v3 = oacc[nf][3]*ivb;
        size_t oa = ((size_t)(b*SEQ + tok_a))*EMB + d;
        size_t ob = ((size_t)(b*SEQ + tok_b))*EMB + d;
        __nv_bfloat16 h0 = __float2bfloat16(v0);
        __nv_bfloat16 h1 = __float2bfloat16(v1);
        __nv_bfloat16 h2 = __float2bfloat16(v2);
        __nv_bfloat16 h3 = __float2bfloat16(v3);
        *(__nv_bfloat162*)(g_Hchi + oa) = __halves2bfloat162(h0, h1);
        *(__nv_bfloat162*)(g_Hchi + ob) = __halves2bfloat162(h2, h3);
        *(__nv_bfloat162*)(g_Hclo + oa) = __halves2bfloat162(
            __float2bfloat16(v0 - __bfloat162float(h0)),
            __float2bfloat16(v1 - __bfloat162float(h1)));
        *(__nv_bfloat162*)(g_Hclo + ob) = __halves2bfloat162(
            __float2bfloat16(v2 - __bfloat162float(h2)),
            __float2bfloat16(v3 - __bfloat162float(h3)));
    }
}

// ---------------------------------------------------------------------------
extern "C" void kernel_launch(void* const* d_in, const int* in_sizes, int n_in,
                              void* d_out, int out_size)
{
    (void)in_sizes; (void)n_in; (void)out_size;
    const float* x  = (const float*)d_in[0];
    const float* Wq = (const float*)d_in[1];
    const float* bq = (const float*)d_in[2];
    const float* Wk = (const float*)d_in[3];
    const float* bk = (const float*)d_in[4];
    const float* Wv = (const float*)d_in[5];
    const float* bv = (const float*)d_in[6];
    const float* Wo = (const float*)d_in[7];
    const float* bo = (const float*)d_in[8];
    float* out = (float*)d_out;

    cudaFuncSetAttribute(qkv_gemm_tc,
                         cudaFuncAttributeMaxDynamicSharedMemorySize,
                         GEMM_SMEM_BYTES);
    cudaFuncSetAttribute(out_gemm_tc,
                         cudaFuncAttributeMaxDynamicSharedMemorySize,
                         GEMM_SMEM_BYTES);
    cudaFuncSetAttribute(attn_mma,
                         cudaFuncAttributeMaxDynamicSharedMemorySize,
                         ATT_SMEM);

    split_kernel<<<dim3(128, 1, 5), 256>>>(x, Wq, Wk, Wv, Wo);
    qkv_gemm_tc<<<dim3(MTOT/128, EMB/128, 3), 256, GEMM_SMEM_BYTES>>>(bq, bk, bv);
    attn_mma<<<dim3(SEQ/128, BHTOT), 256, ATT_SMEM>>>();
    out_gemm_tc<<<dim3(MTOT/128, EMB/128), 256, GEMM_SMEM_BYTES>>>(bo, out);
}

// round 11
// speedup vs baseline: 1.8829x; 1.2058x over previous
#include <cuda_runtime.h>
#include <cuda_fp16.h>
#include <cstdint>

#define SEQ   2048
#define EMB   1024
#define NH    16
#define HD    64
#define BATCH 2
#define MTOT  (BATCH*SEQ)     // 4096
#define BHTOT (BATCH*NH)      // 32

// ---------------- scratch (static device globals; no allocations) ----------
__device__ __half g_Xhi[MTOT*EMB],  g_Xlo[MTOT*EMB];
__device__ __half g_Wqhi[EMB*EMB],  g_Wqlo[EMB*EMB];
__device__ __half g_Wkhi[EMB*EMB],  g_Wklo[EMB*EMB];
__device__ __half g_Wvhi[EMB*EMB];                      // V proj: 2-pass, no lo
__device__ __half g_Wohi[EMB*EMB];                      // out proj: 2-pass, no lo
__device__ __half g_Hchi[MTOT*EMB], g_Hclo[MTOT*EMB];

// Attention operands (fp16 hi/lo). Q has x8 logit scale folded (exact).
__device__ __half g_Qhi[BHTOT*SEQ*HD], g_Qlo[BHTOT*SEQ*HD];
__device__ __half g_Khi[BHTOT*SEQ*HD], g_Klo[BHTOT*SEQ*HD];
// V stored transposed, single fp16: [bh][d][seq]
__device__ __half g_Vt[BHTOT*HD*SEQ];

// ---------------- PTX helpers ----------------------------------------------
__device__ __forceinline__ uint32_t smem_u32(const void* p) {
    uint32_t a;
    asm("{ .reg .u64 t; cvta.to.shared.u64 t, %1; cvt.u32.u64 %0, t; }"
        : "=r"(a) : "l"(p));
    return a;
}
__device__ __forceinline__ void cp16(uint32_t sdst, const void* gsrc) {
    asm volatile("cp.async.cg.shared.global [%0], [%1], 16;"
                 :: "r"(sdst), "l"(gsrc));
}
__device__ __forceinline__ void ldsm_x4(uint32_t a[4], uint32_t addr) {
    asm volatile("ldmatrix.sync.aligned.m8n8.x4.shared.b16 {%0,%1,%2,%3}, [%4];"
                 : "=r"(a[0]), "=r"(a[1]), "=r"(a[2]), "=r"(a[3]) : "r"(addr));
}
__device__ __forceinline__ void ldsm_x2(uint32_t a[2], uint32_t addr) {
    asm volatile("ldmatrix.sync.aligned.m8n8.x2.shared.b16 {%0,%1}, [%2];"
                 : "=r"(a[0]), "=r"(a[1]) : "r"(addr));
}
__device__ __forceinline__ void mma16816(float d[4], const uint32_t a[4],
                                         const uint32_t b[2]) {
    asm volatile(
        "mma.sync.aligned.m16n8k16.row.col.f32.f16.f16.f32 "
        "{%0,%1,%2,%3}, {%4,%5,%6,%7}, {%8,%9}, {%0,%1,%2,%3};"
        : "+f"(d[0]), "+f"(d[1]), "+f"(d[2]), "+f"(d[3])
        : "r"(a[0]), "r"(a[1]), "r"(a[2]), "r"(a[3]), "r"(b[0]), "r"(b[1]));
}
__device__ __forceinline__ uint32_t pack_h2(float a, float b) {
    __half2 t = __floats2half2_rn(a, b);
    return *(uint32_t*)&t;
}

// ---------------- mma.sync GEMM (128x128, 2-stage, 80KB) -------------------
// PASSES=3: acc += Ah*Bh + Ah*Bl + Al*Bh   (residual ~2^-22)
// PASSES=2: acc += Ah*Bh + Al*Bh           (B single fp16, err ~2^-12)
#define BK 32
#define NCHUNK (EMB/BK)       // 32
#define STRB 80               // smem row stride bytes (32 fp16 + 8 pad)
#define OFF_AHI 0
#define OFF_ALO 10240
#define OFF_BHI 20480
#define OFF_BLO 30720
#define STAGE_BYTES 40960
#define GEMM_SMEM_BYTES (2*STAGE_BYTES)   // 80 KB

template<int PASSES>
__device__ __forceinline__ void gemm_load_chunk(
    uint32_t sb, int stage, int kc, int bm, int bn,
    const __half* __restrict__ Ahi, const __half* __restrict__ Alo,
    const __half* __restrict__ Bhi, const __half* __restrict__ Blo,
    int tid)
{
    const uint32_t st = sb + stage * STAGE_BYTES;
#pragma unroll
    for (int i = 0; i < 2; i++) {
        int idx = tid + i * 256;
        int row = idx >> 2, ch = idx & 3;
        uint32_t so = (uint32_t)(row * STRB + ch * 16);
        size_t ga = (size_t)(bm + row) * EMB + kc * BK + ch * 8;
        size_t gb = (size_t)(bn + row) * EMB + kc * BK + ch * 8;
        cp16(st + OFF_AHI + so, Ahi + ga);
        cp16(st + OFF_ALO + so, Alo + ga);
        cp16(st + OFF_BHI + so, Bhi + gb);
        if (PASSES == 3) cp16(st + OFF_BLO + so, Blo + gb);
    }
    asm volatile("cp.async.commit_group;" ::: "memory");
}

template<int PASSES>
__device__ __forceinline__ void gemm_compute_stage(
    uint32_t sbase, int wm, int wn, int lane, float acc[4][4][4])
{
    const int ra      = lane & 15;
    const uint32_t ka = (uint32_t)((lane >> 4) * 16);
    const int nb      = lane & 7;
    const uint32_t kb = (uint32_t)(((lane >> 3) & 1) * 16);
#pragma unroll
    for (int ks = 0; ks < 2; ks++) {
        uint32_t ah[4][4], al[4][4], bh[4][2], bl[4][2];
#pragma unroll
        for (int mi = 0; mi < 4; mi++) {
            uint32_t r = sbase + (uint32_t)((wm*64 + mi*16 + ra) * STRB) + ks*32 + ka;
            ldsm_x4(ah[mi], r + OFF_AHI);
            ldsm_x4(al[mi], r + OFF_ALO);
        }
#pragma unroll
        for (int ni = 0; ni < 4; ni++) {
            uint32_t r = sbase + (uint32_t)((wn*32 + ni*8 + nb) * STRB) + ks*32 + kb;
            ldsm_x2(bh[ni], r + OFF_BHI);
            if (PASSES == 3) ldsm_x2(bl[ni], r + OFF_BLO);
        }
        // pass 0: Ahi * Bhi
#pragma unroll
        for (int mi = 0; mi < 4; mi++)
#pragma unroll
            for (int ni = 0; ni < 4; ni++)
                mma16816(acc[mi][ni], ah[mi], bh[ni]);
        // pass 1 (3-pass only): Ahi * Blo
        if (PASSES == 3) {
#pragma unroll
            for (int mi = 0; mi < 4; mi++)
#pragma unroll
                for (int ni = 0; ni < 4; ni++)
                    mma16816(acc[mi][ni], ah[mi], bl[ni]);
        }
        // pass 2: Alo * Bhi
#pragma unroll
        for (int mi = 0; mi < 4; mi++)
#pragma unroll
            for (int ni = 0; ni < 4; ni++)
                mma16816(acc[mi][ni], al[mi], bh[ni]);
    }
}

template<int PASSES>
__device__ __forceinline__ void gemm_mainloop(
    uint32_t sb, int bm, int bn,
    const __half* Ahi, const __half* Alo,
    const __half* Bhi, const __half* Blo,
    int tid, int wm, int wn, int lane, float acc[4][4][4])
{
#pragma unroll
    for (int mi = 0; mi < 4; mi++)
#pragma unroll
        for (int ni = 0; ni < 4; ni++)
#pragma unroll
            for (int q = 0; q < 4; q++) acc[mi][ni][q] = 0.f;

    gemm_load_chunk<PASSES>(sb, 0, 0, bm, bn, Ahi, Alo, Bhi, Blo, tid);

    for (int c = 0; c < NCHUNK; c++) {
        if (c + 1 < NCHUNK) {
            gemm_load_chunk<PASSES>(sb, (c + 1) & 1, c + 1, bm, bn,
                                    Ahi, Alo, Bhi, Blo, tid);
            asm volatile("cp.async.wait_group 1;" ::: "memory");
        } else {
            asm volatile("cp.async.wait_group 0;" ::: "memory");
        }
        __syncthreads();
        gemm_compute_stage<PASSES>(sb + (uint32_t)((c & 1) * STAGE_BYTES),
                                   wm, wn, lane, acc);
        __syncthreads();
    }
}

// ---------------- split kernel: fp32 -> (fp16 hi, fp16 lo) -----------------
// z=0: x (hi+lo), z=1: Wq (hi+lo), z=2: Wk (hi+lo), z=3: Wv (hi), z=4: Wo (hi)
__global__ __launch_bounds__(256) void split_kernel(
    const float* __restrict__ x,
    const float* __restrict__ Wq, const float* __restrict__ Wk,
    const float* __restrict__ Wv, const float* __restrict__ Wo)
{
    const float* src; __half* hi; __half* lo; int n4; bool wlo;
    switch (blockIdx.z) {
        case 0:  src = x;  hi = g_Xhi;  lo = g_Xlo;  n4 = MTOT*EMB/4; wlo = true;  break;
        case 1:  src = Wq; hi = g_Wqhi; lo = g_Wqlo; n4 = EMB*EMB/4;  wlo = true;  break;
        case 2:  src = Wk; hi = g_Wkhi; lo = g_Wklo; n4 = EMB*EMB/4;  wlo = true;  break;
        case 3:  src = Wv; hi = g_Wvhi; lo = nullptr; n4 = EMB*EMB/4; wlo = false; break;
        default: src = Wo; hi = g_Wohi; lo = nullptr; n4 = EMB*EMB/4; wlo = false; break;
    }
    for (int i = blockIdx.x * blockDim.x + threadIdx.x; i < n4;
         i += gridDim.x * blockDim.x) {
        float4 v = ((const float4*)src)[i];
        __half h0 = __float2half_rn(v.x);
        __half h1 = __float2half_rn(v.y);
        __half h2 = __float2half_rn(v.z);
        __half h3 = __float2half_rn(v.w);
        ((__half2*)hi)[2*i]   = __halves2half2(h0, h1);
        ((__half2*)hi)[2*i+1] = __halves2half2(h2, h3);
        if (wlo) {
            __half l0 = __float2half_rn(v.x - __half2float(h0));
            __half l1 = __float2half_rn(v.y - __half2float(h1));
            __half l2 = __float2half_rn(v.z - __half2float(h2));
            __half l3 = __float2half_rn(v.w - __half2float(h3));
            ((__half2*)lo)[2*i]   = __halves2half2(l0, l1);
            ((__half2*)lo)[2*i+1] = __halves2half2(l2, l3);
        }
    }
}

// ---------------- QKV projection: GEMM + fp16 hi/lo epilogue ----------------
__global__ __launch_bounds__(256) void qkv_gemm_tc(
    const float* __restrict__ bq, const float* __restrict__ bk,
    const float* __restrict__ bv)
{
    extern __shared__ char dsm[];
    uint32_t sb = smem_u32(dsm);
    const int tid = threadIdx.x, wid = tid >> 5, lane = tid & 31;
    const int wm = wid >> 2, wn = wid & 3;
    const int bm = blockIdx.x * 128, bn = blockIdx.y * 128;
    const int z = blockIdx.z;

    float acc[4][4][4];
    const float* bias;
    if (z == 0) {
        bias = bq;
        gemm_mainloop<3>(sb, bm, bn, g_Xhi, g_Xlo, g_Wqhi, g_Wqlo,
                         tid, wm, wn, lane, acc);
    } else if (z == 1) {
        bias = bk;
        gemm_mainloop<3>(sb, bm, bn, g_Xhi, g_Xlo, g_Wkhi, g_Wklo,
                         tid, wm, wn, lane, acc);
    } else {
        bias = bv;
        gemm_mainloop<2>(sb, bm, bn, g_Xhi, g_Xlo, g_Wvhi, nullptr,
                         tid, wm, wn, lane, acc);
    }

    const int g = lane >> 2, tg = lane & 3;
    const float scl = (z == 0) ? 8.0f : 1.0f;
#pragma unroll
    for (int ni = 0; ni < 4; ni++) {
        const int c0 = bn + wn*32 + ni*8 + 2*tg;
        const float bx = bias[c0], by = bias[c0 + 1];
        const int h  = c0 >> 6;
        const int d0 = c0 & 63;
#pragma unroll
        for (int mi = 0; mi < 4; mi++) {
#pragma unroll
            for (int half = 0; half < 2; half++) {
                const int r = bm + wm*64 + mi*16 + g + half*8;
                const int b = r >> 11;
                const int n = r & (SEQ - 1);
                const int bh = (b << 4) + h;
                float v0 = (acc[mi][ni][half*2 + 0] + bx) * scl;
                float v1 = (acc[mi][ni][half*2 + 1] + by) * scl;
                if (z == 2) {
                    // V transposed single fp16: [bh][d][seq]
                    size_t o0 = ((size_t)bh * HD + d0) * SEQ + n;
                    g_Vt[o0]       = __float2half_rn(v0);
                    g_Vt[o0 + SEQ] = __float2half_rn(v1);
                } else {
                    __half h0 = __float2half_rn(v0);
                    __half h1 = __float2half_rn(v1);
                    __half l0 = __float2half_rn(v0 - __half2float(h0));
                    __half l1 = __float2half_rn(v1 - __half2float(h1));
                    size_t o = ((size_t)bh * SEQ + n) * HD + d0;
                    if (z == 0) {
                        *(__half2*)(g_Qhi + o) = __halves2half2(h0, h1);
                        *(__half2*)(g_Qlo + o) = __halves2half2(l0, l1);
                    } else {
                        *(__half2*)(g_Khi + o) = __halves2half2(h0, h1);
                        *(__half2*)(g_Klo + o) = __halves2half2(l0, l1);
                    }
                }
            }
        }
    }
}

// ---------------- output projection (2-pass) --------------------------------
__global__ __launch_bounds__(256) void out_gemm_tc(
    const float* __restrict__ bo, float* __restrict__ outp)
{
    extern __shared__ char dsm[];
    uint32_t sb = smem_u32(dsm);
    const int tid = threadIdx.x, wid = tid >> 5, lane = tid & 31;
    const int wm = wid >> 2, wn = wid & 3;
    const int bm = blockIdx.x * 128, bn = blockIdx.y * 128;

    float acc[4][4][4];
    gemm_mainloop<2>(sb, bm, bn, g_Hchi, g_Hclo, g_Wohi, nullptr,
                     tid, wm, wn, lane, acc);

    const int g = lane >> 2, tg = lane & 3;
#pragma unroll
    for (int ni = 0; ni < 4; ni++) {
        const int c0 = bn + wn*32 + ni*8 + 2*tg;
        const float bx = bo[c0], by = bo[c0 + 1];
#pragma unroll
        for (int mi = 0; mi < 4; mi++) {
#pragma unroll
            for (int half = 0; half < 2; half++) {
                const int r = bm + wm*64 + mi*16 + g + half*8;
                float* op = outp + (size_t)r * EMB + c0;
                float2 v = make_float2(acc[mi][ni][half*2 + 0] + bx,
                                       acc[mi][ni][half*2 + 1] + by);
                *(float2*)op = v;
            }
        }
    }
}

// ---------------- flash attention on HMMA ------------------------------------
// S = QK^T: 3-pass fp16 (Qh*Kh + Ql*Kh + Qh*Kl), PV: 2-pass (Ph*V + Pl*V).
// smem per KV stage: Khi/Klo [64][72B-pad], V [64 d][72B-pad] -> 27 KB/stage.
#define ASTR 144                      // 64 fp16 + 8 pad = 144 B rows
#define AKHI 0
#define AKLO 9216
#define AVS  18432
#define ASTG 27648                    // bytes per stage
#define ATT_SMEM (2*ASTG)             // 54 KB
#define NKT (SEQ/64)                  // 32

__device__ __forceinline__ void att_load_kv(uint32_t sb, int stage, int kt,
                                            int bh, int tid)
{
    const uint32_t st = sb + stage * ASTG;
    const __half* kh = g_Khi + ((size_t)bh*SEQ + kt*64) * HD;
    const __half* kl = g_Klo + ((size_t)bh*SEQ + kt*64) * HD;
    const __half* vt = g_Vt  + (size_t)bh*HD*SEQ + kt*64;
#pragma unroll
    for (int i = 0; i < 2; i++) {
        int idx = tid + i * 256;
        int row = idx >> 3, ch = idx & 7;
        uint32_t so = (uint32_t)(row * ASTR + ch * 16);
        cp16(st + AKHI + so, kh + (size_t)row * HD + ch * 8);
        cp16(st + AKLO + so, kl + (size_t)row * HD + ch * 8);
        cp16(st + AVS  + so, vt + (size_t)row * SEQ + ch * 8);
    }
    asm volatile("cp.async.commit_group;" ::: "memory");
}

__global__ __launch_bounds__(256, 2) void attn_mma()
{
    extern __shared__ char dsm[];
    uint32_t sb = smem_u32(dsm);
    const int tid = threadIdx.x, wid = tid >> 5, lane = tid & 31;
    const int g = lane >> 2, tg = lane & 3;
    const int bh = blockIdx.y, qblk = blockIdx.x;

    // ---- stage Q (hi at sb, lo at sb+18432), capture A-frags ----
    {
        const __half* qh = g_Qhi + ((size_t)bh*SEQ + qblk*128) * HD;
        const __half* ql = g_Qlo + ((size_t)bh*SEQ + qblk*128) * HD;
#pragma unroll
        for (int i = 0; i < 4; i++) {
            int idx = tid + i * 256;
            int row = idx >> 3, ch = idx & 7;
            uint32_t so = (uint32_t)(row * ASTR + ch * 16);
            cp16(sb + so,         qh + (size_t)row * HD + ch * 8);
            cp16(sb + 18432 + so, ql + (size_t)row * HD + ch * 8);
        }
        asm volatile("cp.async.commit_group;" ::: "memory");
        asm volatile("cp.async.wait_group 0;" ::: "memory");
        __syncthreads();
    }
    uint32_t qh[4][4], ql[4][4];
    {
        uint32_t qa = sb + (uint32_t)((wid*16 + (lane & 15)) * ASTR)
                         + (uint32_t)((lane >> 4) * 16);
#pragma unroll
        for (int ks = 0; ks < 4; ks++) {
            ldsm_x4(qh[ks], qa + ks*32);
            ldsm_x4(ql[ks], qa + 18432 + ks*32);
        }
    }
    __syncthreads();   // Q smem free for KV stages

    float oacc[8][4];
#pragma unroll
    for (int nf = 0; nf < 8; nf++)
#pragma unroll
        for (int q = 0; q < 4; q++) oacc[nf][q] = 0.f;
    float m_a = -1e30f, m_b = -1e30f, l_a = 0.f, l_b = 0.f;

    const int nb = lane & 7;
    const uint32_t kb = (uint32_t)(((lane >> 3) & 1) * 16);

    att_load_kv(sb, 0, 0, bh, tid);

    for (int t = 0; t < NKT; t++) {
        if (t + 1 < NKT) {
            att_load_kv(sb, (t + 1) & 1, t + 1, bh, tid);
            asm volatile("cp.async.wait_group 1;" ::: "memory");
        } else {
            asm volatile("cp.async.wait_group 0;" ::: "memory");
        }
        __syncthreads();
        const uint32_t st = sb + (uint32_t)((t & 1) * ASTG);

        // ---- S = Q K^T (3-pass fp16; nf-pairs interleaved) ----
        float sacc[8][4];
#pragma unroll
        for (int nf = 0; nf < 8; nf++)
#pragma unroll
            for (int q = 0; q < 4; q++) sacc[nf][q] = 0.f;

#pragma unroll
        for (int ks = 0; ks < 4; ks++) {
#pragma unroll
            for (int np = 0; np < 4; np++) {
                const int nf0 = 2*np, nf1 = 2*np + 1;
                uint32_t ka0 = st + (uint32_t)((nf0*8 + nb) * ASTR) + kb + ks*32;
                uint32_t ka1 = st + (uint32_t)((nf1*8 + nb) * ASTR) + kb + ks*32;
                uint32_t bh0[2], bl0[2], bh1[2], bl1[2];
                ldsm_x2(bh0, ka0 + AKHI);
                ldsm_x2(bh1, ka1 + AKHI);
                ldsm_x2(bl0, ka0 + AKLO);
                ldsm_x2(bl1, ka1 + AKLO);
                mma16816(sacc[nf0], qh[ks], bh0);
                mma16816(sacc[nf1], qh[ks], bh1);
                mma16816(sacc[nf0], ql[ks], bh0);
                mma16816(sacc[nf1], ql[ks], bh1);
                mma16816(sacc[nf0], qh[ks], bl0);
                mma16816(sacc[nf1], qh[ks], bl1);
            }
        }

        // ---- online softmax (rows g and g+8; reduce over tg lanes) ----
        float mx_a = sacc[0][0], mx_b = sacc[0][2];
#pragma unroll
        for (int nf = 0; nf < 8; nf++) {
            mx_a = fmaxf(mx_a, fmaxf(sacc[nf][0], sacc[nf][1]));
            mx_b = fmaxf(mx_b, fmaxf(sacc[nf][2], sacc[nf][3]));
        }
        mx_a = fmaxf(mx_a, __shfl_xor_sync(0xffffffffu, mx_a, 1));
        mx_a = fmaxf(mx_a, __shfl_xor_sync(0xffffffffu, mx_a, 2));
        mx_b = fmaxf(mx_b, __shfl_xor_sync(0xffffffffu, mx_b, 1));
        mx_b = fmaxf(mx_b, __shfl_xor_sync(0xffffffffu, mx_b, 2));

        float mna = fmaxf(m_a, mx_a), mnb = fmaxf(m_b, mx_b);
        float ala = __expf(m_a - mna), alb = __expf(m_b - mnb);
        m_a = mna; m_b = mnb;

        // exp + fp16 hi/lo split into P A-fragments (C layout == A layout)
        uint32_t phi[4][4], plo[4][4];
        float rs_a = 0.f, rs_b = 0.f;
#pragma unroll
        for (int ks = 0; ks < 4; ks++) {
#pragma unroll
            for (int jj = 0; jj < 2; jj++) {
                const int nf = 2*ks + jj;
                float p0 = __expf(sacc[nf][0] - m_a);
                float p1 = __expf(sacc[nf][1] - m_a);
                float p2 = __expf(sacc[nf][2] - m_b);
                float p3 = __expf(sacc[nf][3] - m_b);
                rs_a += p0 + p1; rs_b += p2 + p3;
                float h0f = __half2float(__float2half_rn(p0));
                float h1f = __half2float(__float2half_rn(p1));
                float h2f = __half2float(__float2half_rn(p2));
                float h3f = __half2float(__float2half_rn(p3));
                phi[ks][2*jj + 0] = pack_h2(h0f, h1f);
                phi[ks][2*jj + 1] = pack_h2(h2f, h3f);
                plo[ks][2*jj + 0] = pack_h2(p0 - h0f, p1 - h1f);
                plo[ks][2*jj + 1] = pack_h2(p2 - h2f, p3 - h3f);
            }
        }
        rs_a += __shfl_xor_sync(0xffffffffu, rs_a, 1);
        rs_a += __shfl_xor_sync(0xffffffffu, rs_a, 2);
        rs_b += __shfl_xor_sync(0xffffffffu, rs_b, 1);
        rs_b += __shfl_xor_sync(0xffffffffu, rs_b, 2);
        l_a = l_a * ala + rs_a;
        l_b = l_b * alb + rs_b;
#pragma unroll
        for (int nf = 0; nf < 8; nf++) {
            oacc[nf][0] *= ala; oacc[nf][1] *= ala;
            oacc[nf][2] *= alb; oacc[nf][3] *= alb;
        }

        // ---- O += P V (2-pass: Ph*V + Pl*V; nf-pairs interleaved) ----
#pragma unroll
        for (int ks = 0; ks < 4; ks++) {
#pragma unroll
            for (int np = 0; np < 4; np++) {
                const int nf0 = 2*np, nf1 = 2*np + 1;
                uint32_t va0 = st + (uint32_t)((nf0*8 + nb) * ASTR) + kb + ks*32;
                uint32_t va1 = st + (uint32_t)((nf1*8 + nb) * ASTR) + kb + ks*32;
                uint32_t vh0[2], vh1[2];
                ldsm_x2(vh0, va0 + AVS);
                ldsm_x2(vh1, va1 + AVS);
                mma16816(oacc[nf0], phi[ks], vh0);
                mma16816(oacc[nf1], phi[ks], vh1);
                mma16816(oacc[nf0], plo[ks], vh0);
                mma16816(oacc[nf1], plo[ks], vh1);
            }
        }
        __syncthreads();
    }

    // ---- epilogue: normalize, emit Hc hi/lo fp16 ----
    const float iva = 1.0f / l_a, ivb = 1.0f / l_b;
    const int b = bh >> 4, h = bh & 15;
    const int tok_a = qblk*128 + wid*16 + g;
    const int tok_b = tok_a + 8;
#pragma unroll
    for (int nf = 0; nf < 8; nf++) {
        const int d = h*HD + nf*8 + 2*tg;
        float v0 = oacc[nf][0]*iva, v1 = oacc[nf][1]*iva;
        float v2 = oacc[nf][2]*ivb, v3 = oacc[nf][3]*ivb;
        size_t oa = ((size_t)(b*SEQ + tok_a))*EMB + d;
        size_t ob = ((size_t)(b*SEQ + tok_b))*EMB + d;
        __half h0 = __float2half_rn(v0);
        __half h1 = __float2half_rn(v1);
        __half h2 = __float2half_rn(v2);
        __half h3 = __float2half_rn(v3);
        *(__half2*)(g_Hchi + oa) = __halves2half2(h0, h1);
        *(__half2*)(g_Hchi + ob) = __halves2half2(h2, h3);
        *(__half2*)(g_Hclo + oa) = __halves2half2(
            __float2half_rn(v0 - __half2float(h0)),
            __float2half_rn(v1 - __half2float(h1)));
        *(__half2*)(g_Hclo + ob) = __halves2half2(
            __float2half_rn(v2 - __half2float(h2)),
            __float2half_rn(v3 - __half2float(h3)));
    }
}

// ---------------------------------------------------------------------------
extern "C" void kernel_launch(void* const* d_in, const int* in_sizes, int n_in,
                              void* d_out, int out_size)
{
    (void)in_sizes; (void)n_in; (void)out_size;
    const float* x  = (const float*)d_in[0];
    const float* Wq = (const float*)d_in[1];
    const float* bq = (const float*)d_in[2];
    const float* Wk = (const float*)d_in[3];
    const float* bk = (const float*)d_in[4];
    const float* Wv = (const float*)d_in[5];
    const float* bv = (const float*)d_in[6];
    const float* Wo = (const float*)d_in[7];
    const float* bo = (const float*)d_in[8];
    float* out = (float*)d_out;

    cudaFuncSetAttribute(qkv_gemm_tc,
                         cudaFuncAttributeMaxDynamicSharedMemorySize,
                         GEMM_SMEM_BYTES);
    cudaFuncSetAttribute(out_gemm_tc,
                         cudaFuncAttributeMaxDynamicSharedMemorySize,
                         GEMM_SMEM_BYTES);
    cudaFuncSetAttribute(attn_mma,
                         cudaFuncAttributeMaxDynamicSharedMemorySize,
                         ATT_SMEM);

    split_kernel<<<dim3(128, 1, 5), 256>>>(x, Wq, Wk, Wv, Wo);
    qkv_gemm_tc<<<dim3(MTOT/128, EMB/128, 3), 256, GEMM_SMEM_BYTES>>>(bq, bk, bv);
    attn_mma<<<dim3(SEQ/128, BHTOT), 256, ATT_SMEM>>>();
    out_gemm_tc<<<dim3(MTOT/128, EMB/128), 256, GEMM_SMEM_BYTES>>>(bo, out);
}

// round 12
// speedup vs baseline: 2.1431x; 1.1382x over previous
#include <cuda_runtime.h>
#include <cuda_fp16.h>
#include <cstdint>

#define SEQ   2048
#define EMB   1024
#define NH    16
#define HD    64
#define BATCH 2
#define MTOT  (BATCH*SEQ)     // 4096
#define BHTOT (BATCH*NH)      // 32

// ---------------- scratch (static device globals; no allocations) ----------
__device__ __half g_Xhi[MTOT*EMB],  g_Xlo[MTOT*EMB];
__device__ __half g_Wqhi[EMB*EMB],  g_Wqlo[EMB*EMB];
__device__ __half g_Wkhi[EMB*EMB],  g_Wklo[EMB*EMB];
__device__ __half g_Wvhi[EMB*EMB];                      // V proj: 1-pass
__device__ __half g_Wohi[EMB*EMB];                      // out proj: 2-pass (A split)
__device__ __half g_Hchi[MTOT*EMB], g_Hclo[MTOT*EMB];

// Attention operands (fp16 hi/lo). Q has x8 logit scale folded (exact).
__device__ __half g_Qhi[BHTOT*SEQ*HD], g_Qlo[BHTOT*SEQ*HD];
__device__ __half g_Khi[BHTOT*SEQ*HD], g_Klo[BHTOT*SEQ*HD];
// V stored transposed, single fp16: [bh][d][seq]
__device__ __half g_Vt[BHTOT*HD*SEQ];

// ---------------- PTX helpers ----------------------------------------------
__device__ __forceinline__ uint32_t smem_u32(const void* p) {
    uint32_t a;
    asm("{ .reg .u64 t; cvta.to.shared.u64 t, %1; cvt.u32.u64 %0, t; }"
        : "=r"(a) : "l"(p));
    return a;
}
__device__ __forceinline__ void cp16(uint32_t sdst, const void* gsrc) {
    asm volatile("cp.async.cg.shared.global [%0], [%1], 16;"
                 :: "r"(sdst), "l"(gsrc));
}
__device__ __forceinline__ void ldsm_x4(uint32_t a[4], uint32_t addr) {
    asm volatile("ldmatrix.sync.aligned.m8n8.x4.shared.b16 {%0,%1,%2,%3}, [%4];"
                 : "=r"(a[0]), "=r"(a[1]), "=r"(a[2]), "=r"(a[3]) : "r"(addr));
}
__device__ __forceinline__ void ldsm_x2(uint32_t a[2], uint32_t addr) {
    asm volatile("ldmatrix.sync.aligned.m8n8.x2.shared.b16 {%0,%1}, [%2];"
                 : "=r"(a[0]), "=r"(a[1]) : "r"(addr));
}
__device__ __forceinline__ void mma16816(float d[4], const uint32_t a[4],
                                         const uint32_t b[2]) {
    asm volatile(
        "mma.sync.aligned.m16n8k16.row.col.f32.f16.f16.f32 "
        "{%0,%1,%2,%3}, {%4,%5,%6,%7}, {%8,%9}, {%0,%1,%2,%3};"
        : "+f"(d[0]), "+f"(d[1]), "+f"(d[2]), "+f"(d[3])
        : "r"(a[0]), "r"(a[1]), "r"(a[2]), "r"(a[3]), "r"(b[0]), "r"(b[1]));
}
__device__ __forceinline__ uint32_t pack_h2(float a, float b) {
    __half2 t = __floats2half2_rn(a, b);
    return *(uint32_t*)&t;
}

// ---------------- mma.sync GEMM (128x128, 2-stage, 80KB) -------------------
// PASSES=3: acc += Ah*Bh + Ah*Bl + Al*Bh   (residual ~2^-22)
// PASSES=2: acc += Ah*Bh + Al*Bh           (B single fp16)
// PASSES=1: acc += Ah*Bh                   (both single fp16)
#define BK 32
#define NCHUNK (EMB/BK)       // 32
#define STRB 80               // smem row stride bytes (32 fp16 + 8 pad)
#define OFF_AHI 0
#define OFF_ALO 10240
#define OFF_BHI 20480
#define OFF_BLO 30720
#define STAGE_BYTES 40960
#define GEMM_SMEM_BYTES (2*STAGE_BYTES)   // 80 KB

template<int PASSES>
__device__ __forceinline__ void gemm_load_chunk(
    uint32_t sb, int stage, int kc, int bm, int bn,
    const __half* __restrict__ Ahi, const __half* __restrict__ Alo,
    const __half* __restrict__ Bhi, const __half* __restrict__ Blo,
    int tid)
{
    const uint32_t st = sb + stage * STAGE_BYTES;
#pragma unroll
    for (int i = 0; i < 2; i++) {
        int idx = tid + i * 256;
        int row = idx >> 2, ch = idx & 3;
        uint32_t so = (uint32_t)(row * STRB + ch * 16);
        size_t ga = (size_t)(bm + row) * EMB + kc * BK + ch * 8;
        size_t gb = (size_t)(bn + row) * EMB + kc * BK + ch * 8;
        cp16(st + OFF_AHI + so, Ahi + ga);
        if (PASSES >= 2) cp16(st + OFF_ALO + so, Alo + ga);
        cp16(st + OFF_BHI + so, Bhi + gb);
        if (PASSES == 3) cp16(st + OFF_BLO + so, Blo + gb);
    }
    asm volatile("cp.async.commit_group;" ::: "memory");
}

template<int PASSES>
__device__ __forceinline__ void gemm_compute_stage(
    uint32_t sbase, int wm, int wn, int lane, float acc[4][4][4])
{
    const int ra      = lane & 15;
    const uint32_t ka = (uint32_t)((lane >> 4) * 16);
    const int nb      = lane & 7;
    const uint32_t kb = (uint32_t)(((lane >> 3) & 1) * 16);
#pragma unroll
    for (int ks = 0; ks < 2; ks++) {
        uint32_t ah[4][4], al[4][4], bh[4][2], bl[4][2];
#pragma unroll
        for (int mi = 0; mi < 4; mi++) {
            uint32_t r = sbase + (uint32_t)((wm*64 + mi*16 + ra) * STRB) + ks*32 + ka;
            ldsm_x4(ah[mi], r + OFF_AHI);
            if (PASSES >= 2) ldsm_x4(al[mi], r + OFF_ALO);
        }
#pragma unroll
        for (int ni = 0; ni < 4; ni++) {
            uint32_t r = sbase + (uint32_t)((wn*32 + ni*8 + nb) * STRB) + ks*32 + kb;
            ldsm_x2(bh[ni], r + OFF_BHI);
            if (PASSES == 3) ldsm_x2(bl[ni], r + OFF_BLO);
        }
        // pass 0: Ahi * Bhi
#pragma unroll
        for (int mi = 0; mi < 4; mi++)
#pragma unroll
            for (int ni = 0; ni < 4; ni++)
                mma16816(acc[mi][ni], ah[mi], bh[ni]);
        // pass 1 (3-pass only): Ahi * Blo
        if (PASSES == 3) {
#pragma unroll
            for (int mi = 0; mi < 4; mi++)
#pragma unroll
                for (int ni = 0; ni < 4; ni++)
                    mma16816(acc[mi][ni], ah[mi], bl[ni]);
        }
        // pass 2 (>=2): Alo * Bhi
        if (PASSES >= 2) {
#pragma unroll
            for (int mi = 0; mi < 4; mi++)
#pragma unroll
                for (int ni = 0; ni < 4; ni++)
                    mma16816(acc[mi][ni], al[mi], bh[ni]);
        }
    }
}

template<int PASSES>
__device__ __forceinline__ void gemm_mainloop(
    uint32_t sb, int bm, int bn,
    const __half* Ahi, const __half* Alo,
    const __half* Bhi, const __half* Blo,
    int tid, int wm, int wn, int lane, float acc[4][4][4])
{
#pragma unroll
    for (int mi = 0; mi < 4; mi++)
#pragma unroll
        for (int ni = 0; ni < 4; ni++)
#pragma unroll
            for (int q = 0; q < 4; q++) acc[mi][ni][q] = 0.f;

    gemm_load_chunk<PASSES>(sb, 0, 0, bm, bn, Ahi, Alo, Bhi, Blo, tid);

    for (int c = 0; c < NCHUNK; c++) {
        if (c + 1 < NCHUNK) {
            gemm_load_chunk<PASSES>(sb, (c + 1) & 1, c + 1, bm, bn,
                                    Ahi, Alo, Bhi, Blo, tid);
            asm volatile("cp.async.wait_group 1;" ::: "memory");
        } else {
            asm volatile("cp.async.wait_group 0;" ::: "memory");
        }
        __syncthreads();
        gemm_compute_stage<PASSES>(sb + (uint32_t)((c & 1) * STAGE_BYTES),
                                   wm, wn, lane, acc);
        __syncthreads();
    }
}

// ---------------- split kernel: fp32 -> (fp16 hi, fp16 lo) -----------------
__global__ __launch_bounds__(256) void split_kernel(
    const float* __restrict__ x,
    const float* __restrict__ Wq, const float* __restrict__ Wk,
    const float* __restrict__ Wv, const float* __restrict__ Wo)
{
    const float* src; __half* hi; __half* lo; int n4; bool wlo;
    switch (blockIdx.z) {
        case 0:  src = x;  hi = g_Xhi;  lo = g_Xlo;  n4 = MTOT*EMB/4; wlo = true;  break;
        case 1:  src = Wq; hi = g_Wqhi; lo = g_Wqlo; n4 = EMB*EMB/4;  wlo = true;  break;
        case 2:  src = Wk; hi = g_Wkhi; lo = g_Wklo; n4 = EMB*EMB/4;  wlo = true;  break;
        case 3:  src = Wv; hi = g_Wvhi; lo = nullptr; n4 = EMB*EMB/4; wlo = false; break;
        default: src = Wo; hi = g_Wohi; lo = nullptr; n4 = EMB*EMB/4; wlo = false; break;
    }
    for (int i = blockIdx.x * blockDim.x + threadIdx.x; i < n4;
         i += gridDim.x * blockDim.x) {
        float4 v = ((const float4*)src)[i];
        __half h0 = __float2half_rn(v.x);
        __half h1 = __float2half_rn(v.y);
        __half h2 = __float2half_rn(v.z);
        __half h3 = __float2half_rn(v.w);
        ((__half2*)hi)[2*i]   = __halves2half2(h0, h1);
        ((__half2*)hi)[2*i+1] = __halves2half2(h2, h3);
        if (wlo) {
            __half l0 = __float2half_rn(v.x - __half2float(h0));
            __half l1 = __float2half_rn(v.y - __half2float(h1));
            __half l2 = __float2half_rn(v.z - __half2float(h2));
            __half l3 = __float2half_rn(v.w - __half2float(h3));
            ((__half2*)lo)[2*i]   = __halves2half2(l0, l1);
            ((__half2*)lo)[2*i+1] = __halves2half2(l2, l3);
        }
    }
}

// ---------------- QKV projection: GEMM + fp16 hi/lo epilogue ----------------
__global__ __launch_bounds__(256) void qkv_gemm_tc(
    const float* __restrict__ bq, const float* __restrict__ bk,
    const float* __restrict__ bv)
{
    extern __shared__ char dsm[];
    uint32_t sb = smem_u32(dsm);
    const int tid = threadIdx.x, wid = tid >> 5, lane = tid & 31;
    const int wm = wid >> 2, wn = wid & 3;
    const int bm = blockIdx.x * 128, bn = blockIdx.y * 128;
    const int z = blockIdx.z;

    float acc[4][4][4];
    const float* bias;
    if (z == 0) {
        bias = bq;
        gemm_mainloop<3>(sb, bm, bn, g_Xhi, g_Xlo, g_Wqhi, g_Wqlo,
                         tid, wm, wn, lane, acc);
    } else if (z == 1) {
        bias = bk;
        gemm_mainloop<3>(sb, bm, bn, g_Xhi, g_Xlo, g_Wkhi, g_Wklo,
                         tid, wm, wn, lane, acc);
    } else {
        bias = bv;
        gemm_mainloop<1>(sb, bm, bn, g_Xhi, nullptr, g_Wvhi, nullptr,
                         tid, wm, wn, lane, acc);
    }

    const int g = lane >> 2, tg = lane & 3;
    const float scl = (z == 0) ? 8.0f : 1.0f;
#pragma unroll
    for (int ni = 0; ni < 4; ni++) {
        const int c0 = bn + wn*32 + ni*8 + 2*tg;
        const float bx = bias[c0], by = bias[c0 + 1];
        const int h  = c0 >> 6;
        const int d0 = c0 & 63;
#pragma unroll
        for (int mi = 0; mi < 4; mi++) {
#pragma unroll
            for (int half = 0; half < 2; half++) {
                const int r = bm + wm*64 + mi*16 + g + half*8;
                const int b = r >> 11;
                const int n = r & (SEQ - 1);
                const int bh = (b << 4) + h;
                float v0 = (acc[mi][ni][half*2 + 0] + bx) * scl;
                float v1 = (acc[mi][ni][half*2 + 1] + by) * scl;
                if (z == 2) {
                    // V transposed single fp16: [bh][d][seq]
                    size_t o0 = ((size_t)bh * HD + d0) * SEQ + n;
                    g_Vt[o0]       = __float2half_rn(v0);
                    g_Vt[o0 + SEQ] = __float2half_rn(v1);
                } else {
                    __half h0 = __float2half_rn(v0);
                    __half h1 = __float2half_rn(v1);
                    __half l0 = __float2half_rn(v0 - __half2float(h0));
                    __half l1 = __float2half_rn(v1 - __half2float(h1));
                    size_t o = ((size_t)bh * SEQ + n) * HD + d0;
                    if (z == 0) {
                        *(__half2*)(g_Qhi + o) = __halves2half2(h0, h1);
                        *(__half2*)(g_Qlo + o) = __halves2half2(l0, l1);
                    } else {
                        *(__half2*)(g_Khi + o) = __halves2half2(h0, h1);
                        *(__half2*)(g_Klo + o) = __halves2half2(l0, l1);
                    }
                }
            }
        }
    }
}

// ---------------- output projection (2-pass) --------------------------------
__global__ __launch_bounds__(256) void out_gemm_tc(
    const float* __restrict__ bo, float* __restrict__ outp)
{
    extern __shared__ char dsm[];
    uint32_t sb = smem_u32(dsm);
    const int tid = threadIdx.x, wid = tid >> 5, lane = tid & 31;
    const int wm = wid >> 2, wn = wid & 3;
    const int bm = blockIdx.x * 128, bn = blockIdx.y * 128;

    float acc[4][4][4];
    gemm_mainloop<2>(sb, bm, bn, g_Hchi, g_Hclo, g_Wohi, nullptr,
                     tid, wm, wn, lane, acc);

    const int g = lane >> 2, tg = lane & 3;
#pragma unroll
    for (int ni = 0; ni < 4; ni++) {
        const int c0 = bn + wn*32 + ni*8 + 2*tg;
        const float bx = bo[c0], by = bo[c0 + 1];
#pragma unroll
        for (int mi = 0; mi < 4; mi++) {
#pragma unroll
            for (int half = 0; half < 2; half++) {
                const int r = bm + wm*64 + mi*16 + g + half*8;
                float* op = outp + (size_t)r * EMB + c0;
                float2 v = make_float2(acc[mi][ni][half*2 + 0] + bx,
                                       acc[mi][ni][half*2 + 1] + by);
                *(float2*)op = v;
            }
        }
    }
}

// ---------------- flash attention on HMMA ------------------------------------
// S = QK^T: 3-pass fp16 (Qh*Kh + Ql*Kh + Qh*Kl).  PV: 1-pass (fp16 P, fp16 V),
// with softmax denominator summed over the ROUNDED fp16 p's so numerator and
// denominator errors cancel in the normalization.
#define ASTR 144                      // 64 fp16 + 8 pad = 144 B rows
#define AKHI 0
#define AKLO 9216
#define AVS  18432
#define ASTG 27648                    // bytes per stage
#define ATT_SMEM (2*ASTG)             // 54 KB
#define NKT (SEQ/64)                  // 32

__device__ __forceinline__ void att_load_kv(uint32_t sb, int stage, int kt,
                                            int bh, int tid)
{
    const uint32_t st = sb + stage * ASTG;
    const __half* kh = g_Khi + ((size_t)bh*SEQ + kt*64) * HD;
    const __half* kl = g_Klo + ((size_t)bh*SEQ + kt*64) * HD;
    const __half* vt = g_Vt  + (size_t)bh*HD*SEQ + kt*64;
#pragma unroll
    for (int i = 0; i < 2; i++) {
        int idx = tid + i * 256;
        int row = idx >> 3, ch = idx & 7;
        uint32_t so = (uint32_t)(row * ASTR + ch * 16);
        cp16(st + AKHI + so, kh + (size_t)row * HD + ch * 8);
        cp16(st + AKLO + so, kl + (size_t)row * HD + ch * 8);
        cp16(st + AVS  + so, vt + (size_t)row * SEQ + ch * 8);
    }
    asm volatile("cp.async.commit_group;" ::: "memory");
}

__global__ __launch_bounds__(256, 2) void attn_mma()
{
    extern __shared__ char dsm[];
    uint32_t sb = smem_u32(dsm);
    const int tid = threadIdx.x, wid = tid >> 5, lane = tid & 31;
    const int g = lane >> 2, tg = lane & 3;
    const int bh = blockIdx.y, qblk = blockIdx.x;

    // ---- stage Q (hi at sb, lo at sb+18432), capture A-frags ----
    {
        const __half* qh = g_Qhi + ((size_t)bh*SEQ + qblk*128) * HD;
        const __half* ql = g_Qlo + ((size_t)bh*SEQ + qblk*128) * HD;
#pragma unroll
        for (int i = 0; i < 4; i++) {
            int idx = tid + i * 256;
            int row = idx >> 3, ch = idx & 7;
            uint32_t so = (uint32_t)(row * ASTR + ch * 16);
            cp16(sb + so,         qh + (size_t)row * HD + ch * 8);
            cp16(sb + 18432 + so, ql + (size_t)row * HD + ch * 8);
        }
        asm volatile("cp.async.commit_group;" ::: "memory");
        asm volatile("cp.async.wait_group 0;" ::: "memory");
        __syncthreads();
    }
    uint32_t qh[4][4], ql[4][4];
    {
        uint32_t qa = sb + (uint32_t)((wid*16 + (lane & 15)) * ASTR)
                         + (uint32_t)((lane >> 4) * 16);
#pragma unroll
        for (int ks = 0; ks < 4; ks++) {
            ldsm_x4(qh[ks], qa + ks*32);
            ldsm_x4(ql[ks], qa + 18432 + ks*32);
        }
    }
    __syncthreads();   // Q smem free for KV stages

    float oacc[8][4];
#pragma unroll
    for (int nf = 0; nf < 8; nf++)
#pragma unroll
        for (int q = 0; q < 4; q++) oacc[nf][q] = 0.f;
    float m_a = -1e30f, m_b = -1e30f, l_a = 0.f, l_b = 0.f;

    const int nb = lane & 7;
    const uint32_t kb = (uint32_t)(((lane >> 3) & 1) * 16);

    att_load_kv(sb, 0, 0, bh, tid);

    for (int t = 0; t < NKT; t++) {
        if (t + 1 < NKT) {
            att_load_kv(sb, (t + 1) & 1, t + 1, bh, tid);
            asm volatile("cp.async.wait_group 1;" ::: "memory");
        } else {
            asm volatile("cp.async.wait_group 0;" ::: "memory");
        }
        __syncthreads();
        const uint32_t st = sb + (uint32_t)((t & 1) * ASTG);

        // ---- S = Q K^T (3-pass fp16; nf-pairs interleaved) ----
        float sacc[8][4];
#pragma unroll
        for (int nf = 0; nf < 8; nf++)
#pragma unroll
            for (int q = 0; q < 4; q++) sacc[nf][q] = 0.f;

#pragma unroll
        for (int ks = 0; ks < 4; ks++) {
#pragma unroll
            for (int np = 0; np < 4; np++) {
                const int nf0 = 2*np, nf1 = 2*np + 1;
                uint32_t ka0 = st + (uint32_t)((nf0*8 + nb) * ASTR) + kb + ks*32;
                uint32_t ka1 = st + (uint32_t)((nf1*8 + nb) * ASTR) + kb + ks*32;
                uint32_t bh0[2], bl0[2], bh1[2], bl1[2];
                ldsm_x2(bh0, ka0 + AKHI);
                ldsm_x2(bh1, ka1 + AKHI);
                ldsm_x2(bl0, ka0 + AKLO);
                ldsm_x2(bl1, ka1 + AKLO);
                mma16816(sacc[nf0], qh[ks], bh0);
                mma16816(sacc[nf1], qh[ks], bh1);
                mma16816(sacc[nf0], ql[ks], bh0);
                mma16816(sacc[nf1], ql[ks], bh1);
                mma16816(sacc[nf0], qh[ks], bl0);
                mma16816(sacc[nf1], qh[ks], bl1);
            }
        }

        // ---- online softmax (rows g and g+8; reduce over tg lanes) ----
        float mx_a = sacc[0][0], mx_b = sacc[0][2];
#pragma unroll
        for (int nf = 0; nf < 8; nf++) {
            mx_a = fmaxf(mx_a, fmaxf(sacc[nf][0], sacc[nf][1]));
            mx_b = fmaxf(mx_b, fmaxf(sacc[nf][2], sacc[nf][3]));
        }
        mx_a = fmaxf(mx_a, __shfl_xor_sync(0xffffffffu, mx_a, 1));
        mx_a = fmaxf(mx_a, __shfl_xor_sync(0xffffffffu, mx_a, 2));
        mx_b = fmaxf(mx_b, __shfl_xor_sync(0xffffffffu, mx_b, 1));
        mx_b = fmaxf(mx_b, __shfl_xor_sync(0xffffffffu, mx_b, 2));

        float mna = fmaxf(m_a, mx_a), mnb = fmaxf(m_b, mx_b);
        float ala = __expf(m_a - mna), alb = __expf(m_b - mnb);
        m_a = mna; m_b = mnb;

        // exp -> fp16 P A-fragments; l sums the ROUNDED values for consistency.
        uint32_t phi[4][4];
        float rs_a = 0.f, rs_b = 0.f;
#pragma unroll
        for (int ks = 0; ks < 4; ks++) {
#pragma unroll
            for (int jj = 0; jj < 2; jj++) {
                const int nf = 2*ks + jj;
                float p0 = __expf(sacc[nf][0] - m_a);
                float p1 = __expf(sacc[nf][1] - m_a);
                float p2 = __expf(sacc[nf][2] - m_b);
                float p3 = __expf(sacc[nf][3] - m_b);
                float h0f = __half2float(__float2half_rn(p0));
                float h1f = __half2float(__float2half_rn(p1));
                float h2f = __half2float(__float2half_rn(p2));
                float h3f = __half2float(__float2half_rn(p3));
                rs_a += h0f + h1f;
                rs_b += h2f + h3f;
                phi[ks][2*jj + 0] = pack_h2(h0f, h1f);
                phi[ks][2*jj + 1] = pack_h2(h2f, h3f);
            }
        }
        rs_a += __shfl_xor_sync(0xffffffffu, rs_a, 1);
        rs_a += __shfl_xor_sync(0xffffffffu, rs_a, 2);
        rs_b += __shfl_xor_sync(0xffffffffu, rs_b, 1);
        rs_b += __shfl_xor_sync(0xffffffffu, rs_b, 2);
        l_a = l_a * ala + rs_a;
        l_b = l_b * alb + rs_b;
#pragma unroll
        for (int nf = 0; nf < 8; nf++) {
            oacc[nf][0] *= ala; oacc[nf][1] *= ala;
            oacc[nf][2] *= alb; oacc[nf][3] *= alb;
        }

        // ---- O += P V (1-pass; nf-pairs interleaved) ----
#pragma unroll
        for (int ks = 0; ks < 4; ks++) {
#pragma unroll
            for (int np = 0; np < 4; np++) {
                const int nf0 = 2*np, nf1 = 2*np + 1;
                uint32_t va0 = st + (uint32_t)((nf0*8 + nb) * ASTR) + kb + ks*32;
                uint32_t va1 = st + (uint32_t)((nf1*8 + nb) * ASTR) + kb + ks*32;
                uint32_t vh0[2], vh1[2];
                ldsm_x2(vh0, va0 + AVS);
                ldsm_x2(vh1, va1 + AVS);
                mma16816(oacc[nf0], phi[ks], vh0);
                mma16816(oacc[nf1], phi[ks], vh1);
            }
        }
        __syncthreads();
    }

    // ---- epilogue: normalize, emit Hc hi/lo fp16 ----
    const float iva = 1.0f / l_a, ivb = 1.0f / l_b;
    const int b = bh >> 4, h = bh & 15;
    const int tok_a = qblk*128 + wid*16 + g;
    const int tok_b = tok_a + 8;
#pragma unroll
    for (int nf = 0; nf < 8; nf++) {
        const int d = h*HD + nf*8 + 2*tg;
        float v0 = oacc[nf][0]*iva, v1 = oacc[nf][1]*iva;
        float v2 = oacc[nf][2]*ivb, v3 = oacc[nf][3]*ivb;
        size_t oa = ((size_t)(b*SEQ + tok_a))*EMB + d;
        size_t ob = ((size_t)(b*SEQ + tok_b))*EMB + d;
        __half h0 = __float2half_rn(v0);
        __half h1 = __float2half_rn(v1);
        __half h2 = __float2half_rn(v2);
        __half h3 = __float2half_rn(v3);
        *(__half2*)(g_Hchi + oa) = __halves2half2(h0, h1);
        *(__half2*)(g_Hchi + ob) = __halves2half2(h2, h3);
        *(__half2*)(g_Hclo + oa) = __halves2half2(
            __float2half_rn(v0 - __half2float(h0)),
            __float2half_rn(v1 - __half2float(h1)));
        *(__half2*)(g_Hclo + ob) = __halves2half2(
            __float2half_rn(v2 - __half2float(h2)),
            __float2half_rn(v3 - __half2float(h3)));
    }
}

// ---------------------------------------------------------------------------
extern "C" void kernel_launch(void* const* d_in, const int* in_sizes, int n_in,
                              void* d_out, int out_size)
{
    (void)in_sizes; (void)n_in; (void)out_size;
    const float* x  = (const float*)d_in[0];
    const float* Wq = (const float*)d_in[1];
    const float* bq = (const float*)d_in[2];
    const float* Wk = (const float*)d_in[3];
    const float* bk = (const float*)d_in[4];
    const float* Wv = (const float*)d_in[5];
    const float* bv = (const float*)d_in[6];
    const float* Wo = (const float*)d_in[7];
    const float* bo = (const float*)d_in[8];
    float* out = (float*)d_out;

    cudaFuncSetAttribute(qkv_gemm_tc,
                         cudaFuncAttributeMaxDynamicSharedMemorySize,
                         GEMM_SMEM_BYTES);
    cudaFuncSetAttribute(out_gemm_tc,
                         cudaFuncAttributeMaxDynamicSharedMemorySize,
                         GEMM_SMEM_BYTES);
    cudaFuncSetAttribute(attn_mma,
                         cudaFuncAttributeMaxDynamicSharedMemorySize,
                         ATT_SMEM);

    split_kernel<<<dim3(128, 1, 5), 256>>>(x, Wq, Wk, Wv, Wo);
    qkv_gemm_tc<<<dim3(MTOT/128, EMB/128, 3), 256, GEMM_SMEM_BYTES>>>(bq, bk, bv);
    attn_mma<<<dim3(SEQ/128, BHTOT), 256, ATT_SMEM>>>();
    out_gemm_tc<<<dim3(MTOT/128, EMB/128), 256, GEMM_SMEM_BYTES>>>(bo, out);
}

// round 14
// speedup vs baseline: 2.2481x; 1.0490x over previous
#include <cuda_runtime.h>
#include <cuda_fp16.h>
#include <cstdint>

#define SEQ   2048
#define EMB   1024
#define NH    16
#define HD    64
#define BATCH 2
#define MTOT  (BATCH*SEQ)     // 4096
#define BHTOT (BATCH*NH)      // 32

// ---------------- scratch (static device globals; no allocations) ----------
__device__ __half g_Xhi[MTOT*EMB],  g_Xlo[MTOT*EMB];
__device__ __half g_Wqhi[EMB*EMB],  g_Wqlo[EMB*EMB];
__device__ __half g_Wkhi[EMB*EMB],  g_Wklo[EMB*EMB];    // K proj: 3-pass (reverted)
__device__ __half g_Wvhi[EMB*EMB];                      // V proj: 1-pass
__device__ __half g_Wohi[EMB*EMB];                      // out proj: 1-pass
__device__ __half g_Hc[MTOT*EMB];                       // single fp16

// Attention operands (fp16 hi/lo for BOTH Q and K — softmax path needs it).
// Q has x8 logit scale folded (exact).
__device__ __half g_Qhi[BHTOT*SEQ*HD], g_Qlo[BHTOT*SEQ*HD];
__device__ __half g_Khi[BHTOT*SEQ*HD], g_Klo[BHTOT*SEQ*HD];
// V stored transposed, single fp16: [bh][d][seq]
__device__ __half g_Vt[BHTOT*HD*SEQ];

// ---------------- PTX helpers ----------------------------------------------
__device__ __forceinline__ uint32_t smem_u32(const void* p) {
    uint32_t a;
    asm("{ .reg .u64 t; cvta.to.shared.u64 t, %1; cvt.u32.u64 %0, t; }"
        : "=r"(a) : "l"(p));
    return a;
}
__device__ __forceinline__ void cp16(uint32_t sdst, const void* gsrc) {
    asm volatile("cp.async.cg.shared.global [%0], [%1], 16;"
                 :: "r"(sdst), "l"(gsrc));
}
__device__ __forceinline__ void ldsm_x4(uint32_t a[4], uint32_t addr) {
    asm volatile("ldmatrix.sync.aligned.m8n8.x4.shared.b16 {%0,%1,%2,%3}, [%4];"
                 : "=r"(a[0]), "=r"(a[1]), "=r"(a[2]), "=r"(a[3]) : "r"(addr));
}
__device__ __forceinline__ void ldsm_x2(uint32_t a[2], uint32_t addr) {
    asm volatile("ldmatrix.sync.aligned.m8n8.x2.shared.b16 {%0,%1}, [%2];"
                 : "=r"(a[0]), "=r"(a[1]) : "r"(addr));
}
__device__ __forceinline__ void mma16816(float d[4], const uint32_t a[4],
                                         const uint32_t b[2]) {
    asm volatile(
        "mma.sync.aligned.m16n8k16.row.col.f32.f16.f16.f32 "
        "{%0,%1,%2,%3}, {%4,%5,%6,%7}, {%8,%9}, {%0,%1,%2,%3};"
        : "+f"(d[0]), "+f"(d[1]), "+f"(d[2]), "+f"(d[3])
        : "r"(a[0]), "r"(a[1]), "r"(a[2]), "r"(a[3]), "r"(b[0]), "r"(b[1]));
}
__device__ __forceinline__ uint32_t pack_h2(float a, float b) {
    __half2 t = __floats2half2_rn(a, b);
    return *(uint32_t*)&t;
}

// ---------------- mma.sync GEMM (128x128, 2-stage, 80KB) -------------------
// PASSES=3: acc += Ah*Bh + Ah*Bl + Al*Bh   (residual ~2^-22)
// PASSES=2: acc += Ah*Bh + Al*Bh           (B single fp16)
// PASSES=1: acc += Ah*Bh                   (both single fp16)
#define BK 32
#define NCHUNK (EMB/BK)       // 32
#define STRB 80               // smem row stride bytes (32 fp16 + 8 pad)
#define OFF_AHI 0
#define OFF_ALO 10240
#define OFF_BHI 20480
#define OFF_BLO 30720
#define STAGE_BYTES 40960
#define GEMM_SMEM_BYTES (2*STAGE_BYTES)   // 80 KB

template<int PASSES>
__device__ __forceinline__ void gemm_load_chunk(
    uint32_t sb, int stage, int kc, int bm, int bn,
    const __half* __restrict__ Ahi, const __half* __restrict__ Alo,
    const __half* __restrict__ Bhi, const __half* __restrict__ Blo,
    int tid)
{
    const uint32_t st = sb + stage * STAGE_BYTES;
#pragma unroll
    for (int i = 0; i < 2; i++) {
        int idx = tid + i * 256;
        int row = idx >> 2, ch = idx & 3;
        uint32_t so = (uint32_t)(row * STRB + ch * 16);
        size_t ga = (size_t)(bm + row) * EMB + kc * BK + ch * 8;
        size_t gb = (size_t)(bn + row) * EMB + kc * BK + ch * 8;
        cp16(st + OFF_AHI + so, Ahi + ga);
        if (PASSES >= 2) cp16(st + OFF_ALO + so, Alo + ga);
        cp16(st + OFF_BHI + so, Bhi + gb);
        if (PASSES == 3) cp16(st + OFF_BLO + so, Blo + gb);
    }
    asm volatile("cp.async.commit_group;" ::: "memory");
}

template<int PASSES>
__device__ __forceinline__ void gemm_compute_stage(
    uint32_t sbase, int wm, int wn, int lane, float acc[4][4][4])
{
    const int ra      = lane & 15;
    const uint32_t ka = (uint32_t)((lane >> 4) * 16);
    const int nb      = lane & 7;
    const uint32_t kb = (uint32_t)(((lane >> 3) & 1) * 16);
#pragma unroll
    for (int ks = 0; ks < 2; ks++) {
        uint32_t ah[4][4], al[4][4], bh[4][2], bl[4][2];
#pragma unroll
        for (int mi = 0; mi < 4; mi++) {
            uint32_t r = sbase + (uint32_t)((wm*64 + mi*16 + ra) * STRB) + ks*32 + ka;
            ldsm_x4(ah[mi], r + OFF_AHI);
            if (PASSES >= 2) ldsm_x4(al[mi], r + OFF_ALO);
        }
#pragma unroll
        for (int ni = 0; ni < 4; ni++) {
            uint32_t r = sbase + (uint32_t)((wn*32 + ni*8 + nb) * STRB) + ks*32 + kb;
            ldsm_x2(bh[ni], r + OFF_BHI);
            if (PASSES == 3) ldsm_x2(bl[ni], r + OFF_BLO);
        }
        // pass 0: Ahi * Bhi
#pragma unroll
        for (int mi = 0; mi < 4; mi++)
#pragma unroll
            for (int ni = 0; ni < 4; ni++)
                mma16816(acc[mi][ni], ah[mi], bh[ni]);
        // pass 1 (3-pass only): Ahi * Blo
        if (PASSES == 3) {
#pragma unroll
            for (int mi = 0; mi < 4; mi++)
#pragma unroll
                for (int ni = 0; ni < 4; ni++)
                    mma16816(acc[mi][ni], ah[mi], bl[ni]);
        }
        // pass 2 (>=2): Alo * Bhi
        if (PASSES >= 2) {
#pragma unroll
            for (int mi = 0; mi < 4; mi++)
#pragma unroll
                for (int ni = 0; ni < 4; ni++)
                    mma16816(acc[mi][ni], al[mi], bh[ni]);
        }
    }
}

template<int PASSES>
__device__ __forceinline__ void gemm_mainloop(
    uint32_t sb, int bm, int bn,
    const __half* Ahi, const __half* Alo,
    const __half* Bhi, const __half* Blo,
    int tid, int wm, int wn, int lane, float acc[4][4][4])
{
#pragma unroll
    for (int mi = 0; mi < 4; mi++)
#pragma unroll
        for (int ni = 0; ni < 4; ni++)
#pragma unroll
            for (int q = 0; q < 4; q++) acc[mi][ni][q] = 0.f;

    gemm_load_chunk<PASSES>(sb, 0, 0, bm, bn, Ahi, Alo, Bhi, Blo, tid);

    for (int c = 0; c < NCHUNK; c++) {
        if (c + 1 < NCHUNK) {
            gemm_load_chunk<PASSES>(sb, (c + 1) & 1, c + 1, bm, bn,
                                    Ahi, Alo, Bhi, Blo, tid);
            asm volatile("cp.async.wait_group 1;" ::: "memory");
        } else {
            asm volatile("cp.async.wait_group 0;" ::: "memory");
        }
        __syncthreads();
        gemm_compute_stage<PASSES>(sb + (uint32_t)((c & 1) * STAGE_BYTES),
                                   wm, wn, lane, acc);
        __syncthreads();
    }
}

// ---------------- split kernel: fp32 -> (fp16 hi [, fp16 lo]) --------------
// z=0: x (hi+lo), z=1: Wq (hi+lo), z=2: Wk (hi+lo), z=3: Wv (hi), z=4: Wo (hi)
__global__ __launch_bounds__(256) void split_kernel(
    const float* __restrict__ x,
    const float* __restrict__ Wq, const float* __restrict__ Wk,
    const float* __restrict__ Wv, const float* __restrict__ Wo)
{
    const float* src; __half* hi; __half* lo; int n4; bool wlo;
    switch (blockIdx.z) {
        case 0:  src = x;  hi = g_Xhi;  lo = g_Xlo;  n4 = MTOT*EMB/4; wlo = true;  break;
        case 1:  src = Wq; hi = g_Wqhi; lo = g_Wqlo; n4 = EMB*EMB/4;  wlo = true;  break;
        case 2:  src = Wk; hi = g_Wkhi; lo = g_Wklo; n4 = EMB*EMB/4;  wlo = true;  break;
        case 3:  src = Wv; hi = g_Wvhi; lo = nullptr; n4 = EMB*EMB/4; wlo = false; break;
        default: src = Wo; hi = g_Wohi; lo = nullptr; n4 = EMB*EMB/4; wlo = false; break;
    }
    for (int i = blockIdx.x * blockDim.x + threadIdx.x; i < n4;
         i += gridDim.x * blockDim.x) {
        float4 v = ((const float4*)src)[i];
        __half h0 = __float2half_rn(v.x);
        __half h1 = __float2half_rn(v.y);
        __half h2 = __float2half_rn(v.z);
        __half h3 = __float2half_rn(v.w);
        ((__half2*)hi)[2*i]   = __halves2half2(h0, h1);
        ((__half2*)hi)[2*i+1] = __halves2half2(h2, h3);
        if (wlo) {
            __half l0 = __float2half_rn(v.x - __half2float(h0));
            __half l1 = __float2half_rn(v.y - __half2float(h1));
            __half l2 = __float2half_rn(v.z - __half2float(h2));
            __half l3 = __float2half_rn(v.w - __half2float(h3));
            ((__half2*)lo)[2*i]   = __halves2half2(l0, l1);
            ((__half2*)lo)[2*i+1] = __halves2half2(l2, l3);
        }
    }
}

// ---------------- QKV projection: GEMM + epilogue ---------------------------
// z=0: Q 3-pass -> hi/lo (x8 folded). z=1: K 3-pass -> hi/lo.
// z=2: V 1-pass -> single fp16 transposed.
__global__ __launch_bounds__(256) void qkv_gemm_tc(
    const float* __restrict__ bq, const float* __restrict__ bk,
    const float* __restrict__ bv)
{
    extern __shared__ char dsm[];
    uint32_t sb = smem_u32(dsm);
    const int tid = threadIdx.x, wid = tid >> 5, lane = tid & 31;
    const int wm = wid >> 2, wn = wid & 3;
    const int bm = blockIdx.x * 128, bn = blockIdx.y * 128;
    const int z = blockIdx.z;

    float acc[4][4][4];
    const float* bias;
    if (z == 0) {
        bias = bq;
        gemm_mainloop<3>(sb, bm, bn, g_Xhi, g_Xlo, g_Wqhi, g_Wqlo,
                         tid, wm, wn, lane, acc);
    } else if (z == 1) {
        bias = bk;
        gemm_mainloop<3>(sb, bm, bn, g_Xhi, g_Xlo, g_Wkhi, g_Wklo,
                         tid, wm, wn, lane, acc);
    } else {
        bias = bv;
        gemm_mainloop<1>(sb, bm, bn, g_Xhi, nullptr, g_Wvhi, nullptr,
                         tid, wm, wn, lane, acc);
    }

    const int g = lane >> 2, tg = lane & 3;
    const float scl = (z == 0) ? 8.0f : 1.0f;
#pragma unroll
    for (int ni = 0; ni < 4; ni++) {
        const int c0 = bn + wn*32 + ni*8 + 2*tg;
        const float bx = bias[c0], by = bias[c0 + 1];
        const int h  = c0 >> 6;
        const int d0 = c0 & 63;
#pragma unroll
        for (int mi = 0; mi < 4; mi++) {
#pragma unroll
            for (int half = 0; half < 2; half++) {
                const int r = bm + wm*64 + mi*16 + g + half*8;
                const int b = r >> 11;
                const int n = r & (SEQ - 1);
                const int bh = (b << 4) + h;
                float v0 = (acc[mi][ni][half*2 + 0] + bx) * scl;
                float v1 = (acc[mi][ni][half*2 + 1] + by) * scl;
                if (z == 2) {
                    // V transposed single fp16: [bh][d][seq]
                    size_t o0 = ((size_t)bh * HD + d0) * SEQ + n;
                    g_Vt[o0]       = __float2half_rn(v0);
                    g_Vt[o0 + SEQ] = __float2half_rn(v1);
                } else {
                    __half h0 = __float2half_rn(v0);
                    __half h1 = __float2half_rn(v1);
                    __half l0 = __float2half_rn(v0 - __half2float(h0));
                    __half l1 = __float2half_rn(v1 - __half2float(h1));
                    size_t o = ((size_t)bh * SEQ + n) * HD + d0;
                    if (z == 0) {
                        *(__half2*)(g_Qhi + o) = __halves2half2(h0, h1);
                        *(__half2*)(g_Qlo + o) = __halves2half2(l0, l1);
                    } else {
                        *(__half2*)(g_Khi + o) = __halves2half2(h0, h1);
                        *(__half2*)(g_Klo + o) = __halves2half2(l0, l1);
                    }
                }
            }
        }
    }
}

// ---------------- output projection (1-pass) --------------------------------
__global__ __launch_bounds__(256) void out_gemm_tc(
    const float* __restrict__ bo, float* __restrict__ outp)
{
    extern __shared__ char dsm[];
    uint32_t sb = smem_u32(dsm);
    const int tid = threadIdx.x, wid = tid >> 5, lane = tid & 31;
    const int wm = wid >> 2, wn = wid & 3;
    const int bm = blockIdx.x * 128, bn = blockIdx.y * 128;

    float acc[4][4][4];
    gemm_mainloop<1>(sb, bm, bn, g_Hc, nullptr, g_Wohi, nullptr,
                     tid, wm, wn, lane, acc);

    const int g = lane >> 2, tg = lane & 3;
#pragma unroll
    for (int ni = 0; ni < 4; ni++) {
        const int c0 = bn + wn*32 + ni*8 + 2*tg;
        const float bx = bo[c0], by = bo[c0 + 1];
#pragma unroll
        for (int mi = 0; mi < 4; mi++) {
#pragma unroll
            for (int half = 0; half < 2; half++) {
                const int r = bm + wm*64 + mi*16 + g + half*8;
                float* op = outp + (size_t)r * EMB + c0;
                float2 v = make_float2(acc[mi][ni][half*2 + 0] + bx,
                                       acc[mi][ni][half*2 + 1] + by);
                *(float2*)op = v;
            }
        }
    }
}

// ---------------- flash attention on HMMA ------------------------------------
// S = QK^T: 3-pass fp16 (Qh*Kh + Ql*Kh + Qh*Kl).  PV: 1-pass (fp16 P, fp16 V),
// with softmax denominator summed over the ROUNDED fp16 p's.
#define ASTR 144                      // 64 fp16 + 8 pad = 144 B rows
#define AKHI 0
#define AKLO 9216
#define AVS  18432
#define ASTG 27648                    // bytes per stage
#define ATT_SMEM (2*ASTG)             // 54 KB
#define NKT (SEQ/64)                  // 32

__device__ __forceinline__ void att_load_kv(uint32_t sb, int stage, int kt,
                                            int bh, int tid)
{
    const uint32_t st = sb + stage * ASTG;
    const __half* kh = g_Khi + ((size_t)bh*SEQ + kt*64) * HD;
    const __half* kl = g_Klo + ((size_t)bh*SEQ + kt*64) * HD;
    const __half* vt = g_Vt  + (size_t)bh*HD*SEQ + kt*64;
#pragma unroll
    for (int i = 0; i < 2; i++) {
        int idx = tid + i * 256;
        int row = idx >> 3, ch = idx & 7;
        uint32_t so = (uint32_t)(row * ASTR + ch * 16);
        cp16(st + AKHI + so, kh + (size_t)row * HD + ch * 8);
        cp16(st + AKLO + so, kl + (size_t)row * HD + ch * 8);
        cp16(st + AVS  + so, vt + (size_t)row * SEQ + ch * 8);
    }
    asm volatile("cp.async.commit_group;" ::: "memory");
}

__global__ __launch_bounds__(256, 2) void attn_mma()
{
    extern __shared__ char dsm[];
    uint32_t sb = smem_u32(dsm);
    const int tid = threadIdx.x, wid = tid >> 5, lane = tid & 31;
    const int g = lane >> 2, tg = lane & 3;
    const int bh = blockIdx.y, qblk = blockIdx.x;

    // ---- stage Q (hi at sb, lo at sb+18432), capture A-frags ----
    {
        const __half* qh = g_Qhi + ((size_t)bh*SEQ + qblk*128) * HD;
        const __half* ql = g_Qlo + ((size_t)bh*SEQ + qblk*128) * HD;
#pragma unroll
        for (int i = 0; i < 4; i++) {
            int idx = tid + i * 256;
            int row = idx >> 3, ch = idx & 7;
            uint32_t so = (uint32_t)(row * ASTR + ch * 16);
            cp16(sb + so,         qh + (size_t)row * HD + ch * 8);
            cp16(sb + 18432 + so, ql + (size_t)row * HD + ch * 8);
        }
        asm volatile("cp.async.commit_group;" ::: "memory");
        asm volatile("cp.async.wait_group 0;" ::: "memory");
        __syncthreads();
    }
    uint32_t qh[4][4], ql[4][4];
    {
        uint32_t qa = sb + (uint32_t)((wid*16 + (lane & 15)) * ASTR)
                         + (uint32_t)((lane >> 4) * 16);
#pragma unroll
        for (int ks = 0; ks < 4; ks++) {
            ldsm_x4(qh[ks], qa + ks*32);
            ldsm_x4(ql[ks], qa + 18432 + ks*32);
        }
    }
    __syncthreads();   // Q smem free for KV stages

    float oacc[8][4];
#pragma unroll
    for (int nf = 0; nf < 8; nf++)
#pragma unroll
        for (int q = 0; q < 4; q++) oacc[nf][q] = 0.f;
    float m_a = -1e30f, m_b = -1e30f, l_a = 0.f, l_b = 0.f;

    const int nb = lane & 7;
    const uint32_t kb = (uint32_t)(((lane >> 3) & 1) * 16);

    att_load_kv(sb, 0, 0, bh, tid);

    for (int t = 0; t < NKT; t++) {
        if (t + 1 < NKT) {
            att_load_kv(sb, (t + 1) & 1, t + 1, bh, tid);
            asm volatile("cp.async.wait_group 1;" ::: "memory");
        } else {
            asm volatile("cp.async.wait_group 0;" ::: "memory");
        }
        __syncthreads();
        const uint32_t st = sb + (uint32_t)((t & 1) * ASTG);

        // ---- S = Q K^T (3-pass fp16; nf-pairs interleaved) ----
        float sacc[8][4];
#pragma unroll
        for (int nf = 0; nf < 8; nf++)
#pragma unroll
            for (int q = 0; q < 4; q++) sacc[nf][q] = 0.f;

#pragma unroll
        for (int ks = 0; ks < 4; ks++) {
#pragma unroll
            for (int np = 0; np < 4; np++) {
                const int nf0 = 2*np, nf1 = 2*np + 1;
                uint32_t ka0 = st + (uint32_t)((nf0*8 + nb) * ASTR) + kb + ks*32;
                uint32_t ka1 = st + (uint32_t)((nf1*8 + nb) * ASTR) + kb + ks*32;
                uint32_t bh0[2], bl0[2], bh1[2], bl1[2];
                ldsm_x2(bh0, ka0 + AKHI);
                ldsm_x2(bh1, ka1 + AKHI);
                ldsm_x2(bl0, ka0 + AKLO);
                ldsm_x2(bl1, ka1 + AKLO);
                mma16816(sacc[nf0], qh[ks], bh0);
                mma16816(sacc[nf1], qh[ks], bh1);
                mma16816(sacc[nf0], ql[ks], bh0);
                mma16816(sacc[nf1], ql[ks], bh1);
                mma16816(sacc[nf0], qh[ks], bl0);
                mma16816(sacc[nf1], qh[ks], bl1);
            }
        }

        // ---- online softmax (rows g and g+8; reduce over tg lanes) ----
        float mx_a = sacc[0][0], mx_b = sacc[0][2];
#pragma unroll
        for (int nf = 0; nf < 8; nf++) {
            mx_a = fmaxf(mx_a, fmaxf(sacc[nf][0], sacc[nf][1]));
            mx_b = fmaxf(mx_b, fmaxf(sacc[nf][2], sacc[nf][3]));
        }
        mx_a = fmaxf(mx_a, __shfl_xor_sync(0xffffffffu, mx_a, 1));
        mx_a = fmaxf(mx_a, __shfl_xor_sync(0xffffffffu, mx_a, 2));
        mx_b = fmaxf(mx_b, __shfl_xor_sync(0xffffffffu, mx_b, 1));
        mx_b = fmaxf(mx_b, __shfl_xor_sync(0xffffffffu, mx_b, 2));

        float mna = fmaxf(m_a, mx_a), mnb = fmaxf(m_b, mx_b);
        float ala = __expf(m_a - mna), alb = __expf(m_b - mnb);
        m_a = mna; m_b = mnb;

        // exp -> fp16 P A-fragments; l sums the ROUNDED values for consistency.
        uint32_t phi[4][4];
        float rs_a = 0.f, rs_b = 0.f;
#pragma unroll
        for (int ks = 0; ks < 4; ks++) {
#pragma unroll
            for (int jj = 0; jj < 2; jj++) {
                const int nf = 2*ks + jj;
                float p0 = __expf(sacc[nf][0] - m_a);
                float p1 = __expf(sacc[nf][1] - m_a);
                float p2 = __expf(sacc[nf][2] - m_b);
                float p3 = __expf(sacc[nf][3] - m_b);
                float h0f = __half2float(__float2half_rn(p0));
                float h1f = __half2float(__float2half_rn(p1));
                float h2f = __half2float(__float2half_rn(p2));
                float h3f = __half2float(__float2half_rn(p3));
                rs_a += h0f + h1f;
                rs_b += h2f + h3f;
                phi[ks][2*jj + 0] = pack_h2(h0f, h1f);
                phi[ks][2*jj + 1] = pack_h2(h2f, h3f);
            }
        }
        rs_a += __shfl_xor_sync(0xffffffffu, rs_a, 1);
        rs_a += __shfl_xor_sync(0xffffffffu, rs_a, 2);
        rs_b += __shfl_xor_sync(0xffffffffu, rs_b, 1);
        rs_b += __shfl_xor_sync(0xffffffffu, rs_b, 2);
        l_a = l_a * ala + rs_a;
        l_b = l_b * alb + rs_b;
#pragma unroll
        for (int nf = 0; nf < 8; nf++) {
            oacc[nf][0] *= ala; oacc[nf][1] *= ala;
            oacc[nf][2] *= alb; oacc[nf][3] *= alb;
        }

        // ---- O += P V (1-pass; nf-pairs interleaved) ----
#pragma unroll
        for (int ks = 0; ks < 4; ks++) {
#pragma unroll
            for (int np = 0; np < 4; np++) {
                const int nf0 = 2*np, nf1 = 2*np + 1;
                uint32_t va0 = st + (uint32_t)((nf0*8 + nb) * ASTR) + kb + ks*32;
                uint32_t va1 = st + (uint32_t)((nf1*8 + nb) * ASTR) + kb + ks*32;
                uint32_t vh0[2], vh1[2];
                ldsm_x2(vh0, va0 + AVS);
                ldsm_x2(vh1, va1 + AVS);
                mma16816(oacc[nf0], phi[ks], vh0);
                mma16816(oacc[nf1], phi[ks], vh1);
            }
        }
        __syncthreads();
    }

    // ---- epilogue: normalize, emit Hc single fp16 ----
    const float iva = 1.0f / l_a, ivb = 1.0f / l_b;
    const int b = bh >> 4, h = bh & 15;
    const int tok_a = qblk*128 + wid*16 + g;
    const int tok_b = tok_a + 8;
#pragma unroll
    for (int nf = 0; nf < 8; nf++) {
        const int d = h*HD + nf*8 + 2*tg;
        float v0 = oacc[nf][0]*iva, v1 = oacc[nf][1]*iva;
        float v2 = oacc[nf][2]*ivb, v3 = oacc[nf][3]*ivb;
        size_t oa = ((size_t)(b*SEQ + tok_a))*EMB + d;
        size_t ob = ((size_t)(b*SEQ + tok_b))*EMB + d;
        *(__half2*)(g_Hc + oa) =
            __halves2half2(__float2half_rn(v0), __float2half_rn(v1));
        *(__half2*)(g_Hc + ob) =
            __halves2half2(__float2half_rn(v2), __float2half_rn(v3));
    }
}

// ---------------------------------------------------------------------------
extern "C" void kernel_launch(void* const* d_in, const int* in_sizes, int n_in,
                              void* d_out, int out_size)
{
    (void)in_sizes; (void)n_in; (void)out_size;
    const float* x  = (const float*)d_in[0];
    const float* Wq = (const float*)d_in[1];
    const float* bq = (const float*)d_in[2];
    const float* Wk = (const float*)d_in[3];
    const float* bk = (const float*)d_in[4];
    const float* Wv = (const float*)d_in[5];
    const float* bv = (const float*)d_in[6];
    const float* Wo = (const float*)d_in[7];
    const float* bo = (const float*)d_in[8];
    float* out = (float*)d_out;

    cudaFuncSetAttribute(qkv_gemm_tc,
                         cudaFuncAttributeMaxDynamicSharedMemorySize,
                         GEMM_SMEM_BYTES);
    cudaFuncSetAttribute(out_gemm_tc,
                         cudaFuncAttributeMaxDynamicSharedMemorySize,
                         GEMM_SMEM_BYTES);
    cudaFuncSetAttribute(attn_mma,
                         cudaFuncAttributeMaxDynamicSharedMemorySize,
                         ATT_SMEM);

    split_kernel<<<dim3(128, 1, 5), 256>>>(x, Wq, Wk, Wv, Wo);
    qkv_gemm_tc<<<dim3(MTOT/128, EMB/128, 3), 256, GEMM_SMEM_BYTES>>>(bq, bk, bv);
    attn_mma<<<dim3(SEQ/128, BHTOT), 256, ATT_SMEM>>>();
    out_gemm_tc<<<dim3(MTOT/128, EMB/128), 256, GEMM_SMEM_BYTES>>>(bo, out);
}

// round 15
// speedup vs baseline: 2.3189x; 1.0315x over previous
#include <cuda_runtime.h>
#include <cuda_fp16.h>
#include <cstdint>

#define SEQ   2048
#define EMB   1024
#define NH    16
#define HD    64
#define BATCH 2
#define MTOT  (BATCH*SEQ)     // 4096
#define BHTOT (BATCH*NH)      // 32

// ---------------- scratch (static device globals; no allocations) ----------
__device__ __half g_Xhi[MTOT*EMB],  g_Xlo[MTOT*EMB];
__device__ __half g_Wqhi[EMB*EMB],  g_Wqlo[EMB*EMB];
__device__ __half g_Wkhi[EMB*EMB],  g_Wklo[EMB*EMB];
__device__ __half g_Wvhi[EMB*EMB];                      // V proj: 1-pass
__device__ __half g_Wohi[EMB*EMB];                      // out proj: 1-pass
__device__ __half g_Hc[MTOT*EMB];                       // single fp16

// Attention operands (fp16 hi/lo for BOTH Q and K — softmax path needs it).
// Q has x8 logit scale folded (exact).
__device__ __half g_Qhi[BHTOT*SEQ*HD], g_Qlo[BHTOT*SEQ*HD];
__device__ __half g_Khi[BHTOT*SEQ*HD], g_Klo[BHTOT*SEQ*HD];
// V stored transposed, single fp16: [bh][d][seq]
__device__ __half g_Vt[BHTOT*HD*SEQ];

// ---------------- PTX helpers ----------------------------------------------
__device__ __forceinline__ uint32_t smem_u32(const void* p) {
    uint32_t a;
    asm("{ .reg .u64 t; cvta.to.shared.u64 t, %1; cvt.u32.u64 %0, t; }"
        : "=r"(a) : "l"(p));
    return a;
}
__device__ __forceinline__ void cp16(uint32_t sdst, const void* gsrc) {
    asm volatile("cp.async.cg.shared.global [%0], [%1], 16;"
                 :: "r"(sdst), "l"(gsrc));
}
__device__ __forceinline__ void ldsm_x4(uint32_t a[4], uint32_t addr) {
    asm volatile("ldmatrix.sync.aligned.m8n8.x4.shared.b16 {%0,%1,%2,%3}, [%4];"
                 : "=r"(a[0]), "=r"(a[1]), "=r"(a[2]), "=r"(a[3]) : "r"(addr));
}
__device__ __forceinline__ void mma16816(float d[4], const uint32_t a[4],
                                         const uint32_t b[2]) {
    asm volatile(
        "mma.sync.aligned.m16n8k16.row.col.f32.f16.f16.f32 "
        "{%0,%1,%2,%3}, {%4,%5,%6,%7}, {%8,%9}, {%0,%1,%2,%3};"
        : "+f"(d[0]), "+f"(d[1]), "+f"(d[2]), "+f"(d[3])
        : "r"(a[0]), "r"(a[1]), "r"(a[2]), "r"(a[3]), "r"(b[0]), "r"(b[1]));
}
__device__ __forceinline__ uint32_t pack_h2(float a, float b) {
    __half2 t = __floats2half2_rn(a, b);
    return *(uint32_t*)&t;
}

// ---------------- mma.sync GEMM (128x128, 2-stage, 80KB) -------------------
// PASSES=3: acc += Ah*Bh + Ah*Bl + Al*Bh   (residual ~2^-22)
// PASSES=2: acc += Ah*Bh + Al*Bh           (B single fp16)
// PASSES=1: acc += Ah*Bh                   (both single fp16)
#define BK 32
#define NCHUNK (EMB/BK)       // 32
#define STRB 80               // smem row stride bytes (32 fp16 + 8 pad)
#define OFF_AHI 0
#define OFF_ALO 10240
#define OFF_BHI 20480
#define OFF_BLO 30720
#define STAGE_BYTES 40960
#define GEMM_SMEM_BYTES (2*STAGE_BYTES)   // 80 KB

template<int PASSES>
__device__ __forceinline__ void gemm_load_chunk(
    uint32_t sb, int stage, int kc, int bm, int bn,
    const __half* __restrict__ Ahi, const __half* __restrict__ Alo,
    const __half* __restrict__ Bhi, const __half* __restrict__ Blo,
    int tid)
{
    const uint32_t st = sb + stage * STAGE_BYTES;
#pragma unroll
    for (int i = 0; i < 2; i++) {
        int idx = tid + i * 256;
        int row = idx >> 2, ch = idx & 3;
        uint32_t so = (uint32_t)(row * STRB + ch * 16);
        size_t ga = (size_t)(bm + row) * EMB + kc * BK + ch * 8;
        size_t gb = (size_t)(bn + row) * EMB + kc * BK + ch * 8;
        cp16(st + OFF_AHI + so, Ahi + ga);
        if (PASSES >= 2) cp16(st + OFF_ALO + so, Alo + ga);
        cp16(st + OFF_BHI + so, Bhi + gb);
        if (PASSES == 3) cp16(st + OFF_BLO + so, Blo + gb);
    }
    asm volatile("cp.async.commit_group;" ::: "memory");
}

// B fragments fetched as ldmatrix.x4 over 16-row groups (2 n-frags per instr).
template<int PASSES>
__device__ __forceinline__ void gemm_compute_stage(
    uint32_t sbase, int wm, int wn, int lane, float acc[4][4][4])
{
    const int ra      = lane & 15;
    const uint32_t ka = (uint32_t)((lane >> 4) * 16);
    const int rb      = ((lane >> 4) << 3) + (lane & 7);
    const uint32_t kb = (uint32_t)(((lane >> 3) & 1) * 16);
#pragma unroll
    for (int ks = 0; ks < 2; ks++) {
        uint32_t ah[4][4], al[4][4], bh[2][4], bl[2][4];
#pragma unroll
        for (int mi = 0; mi < 4; mi++) {
            uint32_t r = sbase + (uint32_t)((wm*64 + mi*16 + ra) * STRB) + ks*32 + ka;
            ldsm_x4(ah[mi], r + OFF_AHI);
            if (PASSES >= 2) ldsm_x4(al[mi], r + OFF_ALO);
        }
#pragma unroll
        for (int nj = 0; nj < 2; nj++) {
            uint32_t r = sbase + (uint32_t)((wn*32 + nj*16 + rb) * STRB) + ks*32 + kb;
            ldsm_x4(bh[nj], r + OFF_BHI);
            if (PASSES == 3) ldsm_x4(bl[nj], r + OFF_BLO);
        }
        // pass 0: Ahi * Bhi
#pragma unroll
        for (int mi = 0; mi < 4; mi++)
#pragma unroll
            for (int nj = 0; nj < 2; nj++) {
                mma16816(acc[mi][2*nj],   ah[mi], bh[nj]);
                mma16816(acc[mi][2*nj+1], ah[mi], bh[nj] + 2);
            }
        // pass 1 (3-pass only): Ahi * Blo
        if (PASSES == 3) {
#pragma unroll
            for (int mi = 0; mi < 4; mi++)
#pragma unroll
                for (int nj = 0; nj < 2; nj++) {
                    mma16816(acc[mi][2*nj],   ah[mi], bl[nj]);
                    mma16816(acc[mi][2*nj+1], ah[mi], bl[nj] + 2);
                }
        }
        // pass 2 (>=2): Alo * Bhi
        if (PASSES >= 2) {
#pragma unroll
            for (int mi = 0; mi < 4; mi++)
#pragma unroll
                for (int nj = 0; nj < 2; nj++) {
                    mma16816(acc[mi][2*nj],   al[mi], bh[nj]);
                    mma16816(acc[mi][2*nj+1], al[mi], bh[nj] + 2);
                }
        }
    }
}

// Single-sync pipeline: wait(load c) -> sync -> issue load(c+1) -> compute(c).
// load(c+1) writes the opposite stage of compute(c); the sync orders it
// against compute(c-1)'s reads of that stage.
template<int PASSES>
__device__ __forceinline__ void gemm_mainloop(
    uint32_t sb, int bm, int bn,
    const __half* Ahi, const __half* Alo,
    const __half* Bhi, const __half* Blo,
    int tid, int wm, int wn, int lane, float acc[4][4][4])
{
#pragma unroll
    for (int mi = 0; mi < 4; mi++)
#pragma unroll
        for (int ni = 0; ni < 4; ni++)
#pragma unroll
            for (int q = 0; q < 4; q++) acc[mi][ni][q] = 0.f;

    gemm_load_chunk<PASSES>(sb, 0, 0, bm, bn, Ahi, Alo, Bhi, Blo, tid);

    for (int c = 0; c < NCHUNK; c++) {
        asm volatile("cp.async.wait_group 0;" ::: "memory");
        __syncthreads();
        if (c + 1 < NCHUNK)
            gemm_load_chunk<PASSES>(sb, (c + 1) & 1, c + 1, bm, bn,
                                    Ahi, Alo, Bhi, Blo, tid);
        gemm_compute_stage<PASSES>(sb + (uint32_t)((c & 1) * STAGE_BYTES),
                                   wm, wn, lane, acc);
    }
}

// ---------------- split kernel: fp32 -> (fp16 hi [, fp16 lo]) --------------
__global__ __launch_bounds__(256) void split_kernel(
    const float* __restrict__ x,
    const float* __restrict__ Wq, const float* __restrict__ Wk,
    const float* __restrict__ Wv, const float* __restrict__ Wo)
{
    const float* src; __half* hi; __half* lo; int n4; bool wlo;
    switch (blockIdx.z) {
        case 0:  src = x;  hi = g_Xhi;  lo = g_Xlo;  n4 = MTOT*EMB/4; wlo = true;  break;
        case 1:  src = Wq; hi = g_Wqhi; lo = g_Wqlo; n4 = EMB*EMB/4;  wlo = true;  break;
        case 2:  src = Wk; hi = g_Wkhi; lo = g_Wklo; n4 = EMB*EMB/4;  wlo = true;  break;
        case 3:  src = Wv; hi = g_Wvhi; lo = nullptr; n4 = EMB*EMB/4; wlo = false; break;
        default: src = Wo; hi = g_Wohi; lo = nullptr; n4 = EMB*EMB/4; wlo = false; break;
    }
    for (int i = blockIdx.x * blockDim.x + threadIdx.x; i < n4;
         i += gridDim.x * blockDim.x) {
        float4 v = ((const float4*)src)[i];
        __half h0 = __float2half_rn(v.x);
        __half h1 = __float2half_rn(v.y);
        __half h2 = __float2half_rn(v.z);
        __half h3 = __float2half_rn(v.w);
        ((__half2*)hi)[2*i]   = __halves2half2(h0, h1);
        ((__half2*)hi)[2*i+1] = __halves2half2(h2, h3);
        if (wlo) {
            __half l0 = __float2half_rn(v.x - __half2float(h0));
            __half l1 = __float2half_rn(v.y - __half2float(h1));
            __half l2 = __float2half_rn(v.z - __half2float(h2));
            __half l3 = __float2half_rn(v.w - __half2float(h3));
            ((__half2*)lo)[2*i]   = __halves2half2(l0, l1);
            ((__half2*)lo)[2*i+1] = __halves2half2(l2, l3);
        }
    }
}

// ---------------- QKV projection: GEMM + epilogue ---------------------------
__global__ __launch_bounds__(256) void qkv_gemm_tc(
    const float* __restrict__ bq, const float* __restrict__ bk,
    const float* __restrict__ bv)
{
    extern __shared__ char dsm[];
    uint32_t sb = smem_u32(dsm);
    const int tid = threadIdx.x, wid = tid >> 5, lane = tid & 31;
    const int wm = wid >> 2, wn = wid & 3;
    const int bm = blockIdx.x * 128, bn = blockIdx.y * 128;
    const int z = blockIdx.z;

    float acc[4][4][4];
    const float* bias;
    if (z == 0) {
        bias = bq;
        gemm_mainloop<3>(sb, bm, bn, g_Xhi, g_Xlo, g_Wqhi, g_Wqlo,
                         tid, wm, wn, lane, acc);
    } else if (z == 1) {
        bias = bk;
        gemm_mainloop<3>(sb, bm, bn, g_Xhi, g_Xlo, g_Wkhi, g_Wklo,
                         tid, wm, wn, lane, acc);
    } else {
        bias = bv;
        gemm_mainloop<1>(sb, bm, bn, g_Xhi, nullptr, g_Wvhi, nullptr,
                         tid, wm, wn, lane, acc);
    }

    const int g = lane >> 2, tg = lane & 3;
    const float scl = (z == 0) ? 8.0f : 1.0f;
#pragma unroll
    for (int ni = 0; ni < 4; ni++) {
        const int c0 = bn + wn*32 + ni*8 + 2*tg;
        const float bx = bias[c0], by = bias[c0 + 1];
        const int h  = c0 >> 6;
        const int d0 = c0 & 63;
#pragma unroll
        for (int mi = 0; mi < 4; mi++) {
#pragma unroll
            for (int half = 0; half < 2; half++) {
                const int r = bm + wm*64 + mi*16 + g + half*8;
                const int b = r >> 11;
                const int n = r & (SEQ - 1);
                const int bh = (b << 4) + h;
                float v0 = (acc[mi][ni][half*2 + 0] + bx) * scl;
                float v1 = (acc[mi][ni][half*2 + 1] + by) * scl;
                if (z == 2) {
                    // V transposed single fp16: [bh][d][seq]
                    size_t o0 = ((size_t)bh * HD + d0) * SEQ + n;
                    g_Vt[o0]       = __float2half_rn(v0);
                    g_Vt[o0 + SEQ] = __float2half_rn(v1);
                } else {
                    __half h0 = __float2half_rn(v0);
                    __half h1 = __float2half_rn(v1);
                    __half l0 = __float2half_rn(v0 - __half2float(h0));
                    __half l1 = __float2half_rn(v1 - __half2float(h1));
                    size_t o = ((size_t)bh * SEQ + n) * HD + d0;
                    if (z == 0) {
                        *(__half2*)(g_Qhi + o) = __halves2half2(h0, h1);
                        *(__half2*)(g_Qlo + o) = __halves2half2(l0, l1);
                    } else {
                        *(__half2*)(g_Khi + o) = __halves2half2(h0, h1);
                        *(__half2*)(g_Klo + o) = __halves2half2(l0, l1);
                    }
                }
            }
        }
    }
}

// ---------------- output projection (1-pass) --------------------------------
__global__ __launch_bounds__(256) void out_gemm_tc(
    const float* __restrict__ bo, float* __restrict__ outp)
{
    extern __shared__ char dsm[];
    uint32_t sb = smem_u32(dsm);
    const int tid = threadIdx.x, wid = tid >> 5, lane = tid & 31;
    const int wm = wid >> 2, wn = wid & 3;
    const int bm = blockIdx.x * 128, bn = blockIdx.y * 128;

    float acc[4][4][4];
    gemm_mainloop<1>(sb, bm, bn, g_Hc, nullptr, g_Wohi, nullptr,
                     tid, wm, wn, lane, acc);

    const int g = lane >> 2, tg = lane & 3;
#pragma unroll
    for (int ni = 0; ni < 4; ni++) {
        const int c0 = bn + wn*32 + ni*8 + 2*tg;
        const float bx = bo[c0], by = bo[c0 + 1];
#pragma unroll
        for (int mi = 0; mi < 4; mi++) {
#pragma unroll
            for (int half = 0; half < 2; half++) {
                const int r = bm + wm*64 + mi*16 + g + half*8;
                float* op = outp + (size_t)r * EMB + c0;
                float2 v = make_float2(acc[mi][ni][half*2 + 0] + bx,
                                       acc[mi][ni][half*2 + 1] + by);
                *(float2*)op = v;
            }
        }
    }
}

// ---------------- flash attention on HMMA ------------------------------------
// S = QK^T: 3-pass fp16 (Qh*Kh + Ql*Kh + Qh*Kl).  PV: 1-pass.
// All K/V fragments fetched via ldmatrix.x4 over 16-row groups.
#define ASTR 144                      // 64 fp16 + 8 pad = 144 B rows
#define AKHI 0
#define AKLO 9216
#define AVS  18432
#define ASTG 27648                    // bytes per stage
#define ATT_SMEM (2*ASTG)             // 54 KB
#define NKT (SEQ/64)                  // 32

__device__ __forceinline__ void att_load_kv(uint32_t sb, int stage, int kt,
                                            int bh, int tid)
{
    const uint32_t st = sb + stage * ASTG;
    const __half* kh = g_Khi + ((size_t)bh*SEQ + kt*64) * HD;
    const __half* kl = g_Klo + ((size_t)bh*SEQ + kt*64) * HD;
    const __half* vt = g_Vt  + (size_t)bh*HD*SEQ + kt*64;
#pragma unroll
    for (int i = 0; i < 2; i++) {
        int idx = tid + i * 256;
        int row = idx >> 3, ch = idx & 7;
        uint32_t so = (uint32_t)(row * ASTR + ch * 16);
        cp16(st + AKHI + so, kh + (size_t)row * HD + ch * 8);
        cp16(st + AKLO + so, kl + (size_t)row * HD + ch * 8);
        cp16(st + AVS  + so, vt + (size_t)row * SEQ + ch * 8);
    }
    asm volatile("cp.async.commit_group;" ::: "memory");
}

__global__ __launch_bounds__(256, 2) void attn_mma()
{
    extern __shared__ char dsm[];
    uint32_t sb = smem_u32(dsm);
    const int tid = threadIdx.x, wid = tid >> 5, lane = tid & 31;
    const int g = lane >> 2, tg = lane & 3;
    const int bh = blockIdx.y, qblk = blockIdx.x;

    // ---- stage Q (hi at sb, lo at sb+18432), capture A-frags ----
    {
        const __half* qh = g_Qhi + ((size_t)bh*SEQ + qblk*128) * HD;
        const __half* ql = g_Qlo + ((size_t)bh*SEQ + qblk*128) * HD;
#pragma unroll
        for (int i = 0; i < 4; i++) {
            int idx = tid + i * 256;
            int row = idx >> 3, ch = idx & 7;
            uint32_t so = (uint32_t)(row * ASTR + ch * 16);
            cp16(sb + so,         qh + (size_t)row * HD + ch * 8);
            cp16(sb + 18432 + so, ql + (size_t)row * HD + ch * 8);
        }
        asm volatile("cp.async.commit_group;" ::: "memory");
        asm volatile("cp.async.wait_group 0;" ::: "memory");
        __syncthreads();
    }
    uint32_t qh[4][4], ql[4][4];
    {
        uint32_t qa = sb + (uint32_t)((wid*16 + (lane & 15)) * ASTR)
                         + (uint32_t)((lane >> 4) * 16);
#pragma unroll
        for (int ks = 0; ks < 4; ks++) {
            ldsm_x4(qh[ks], qa + ks*32);
            ldsm_x4(ql[ks], qa + 18432 + ks*32);
        }
    }
    __syncthreads();   // Q smem free for KV stages

    float oacc[8][4];
#pragma unroll
    for (int nf = 0; nf < 8; nf++)
#pragma unroll
        for (int q = 0; q < 4; q++) oacc[nf][q] = 0.f;
    float m_a = -1e30f, m_b = -1e30f, l_a = 0.f, l_b = 0.f;

    // x4 B-fragment addressing (same pattern as GEMM): 16-row groups.
    const int rb      = ((lane >> 4) << 3) + (lane & 7);
    const uint32_t kb = (uint32_t)(((lane >> 3) & 1) * 16);

    att_load_kv(sb, 0, 0, bh, tid);

    for (int t = 0; t < NKT; t++) {
        asm volatile("cp.async.wait_group 0;" ::: "memory");
        __syncthreads();
        if (t + 1 < NKT)
            att_load_kv(sb, (t + 1) & 1, t + 1, bh, tid);
        const uint32_t st = sb + (uint32_t)((t & 1) * ASTG);

        // ---- S = Q K^T (3-pass fp16; x4 K fragments) ----
        float sacc[8][4];
#pragma unroll
        for (int nf = 0; nf < 8; nf++)
#pragma unroll
            for (int q = 0; q < 4; q++) sacc[nf][q] = 0.f;

#pragma unroll
        for (int ks = 0; ks < 4; ks++) {
#pragma unroll
            for (int np = 0; np < 4; np++) {
                const int nf0 = 2*np, nf1 = 2*np + 1;
                uint32_t ka = st + (uint32_t)((np*16 + rb) * ASTR) + kb + ks*32;
                uint32_t kh4[4], kl4[4];
                ldsm_x4(kh4, ka + AKHI);
                ldsm_x4(kl4, ka + AKLO);
                mma16816(sacc[nf0], qh[ks], kh4);
                mma16816(sacc[nf1], qh[ks], kh4 + 2);
                mma16816(sacc[nf0], ql[ks], kh4);
                mma16816(sacc[nf1], ql[ks], kh4 + 2);
                mma16816(sacc[nf0], qh[ks], kl4);
                mma16816(sacc[nf1], qh[ks], kl4 + 2);
            }
        }

        // ---- online softmax (rows g and g+8; reduce over tg lanes) ----
        float mx_a = sacc[0][0], mx_b = sacc[0][2];
#pragma unroll
        for (int nf = 0; nf < 8; nf++) {
            mx_a = fmaxf(mx_a, fmaxf(sacc[nf][0], sacc[nf][1]));
            mx_b = fmaxf(mx_b, fmaxf(sacc[nf][2], sacc[nf][3]));
        }
        mx_a = fmaxf(mx_a, __shfl_xor_sync(0xffffffffu, mx_a, 1));
        mx_a = fmaxf(mx_a, __shfl_xor_sync(0xffffffffu, mx_a, 2));
        mx_b = fmaxf(mx_b, __shfl_xor_sync(0xffffffffu, mx_b, 1));
        mx_b = fmaxf(mx_b, __shfl_xor_sync(0xffffffffu, mx_b, 2));

        float mna = fmaxf(m_a, mx_a), mnb = fmaxf(m_b, mx_b);
        float ala = __expf(m_a - mna), alb = __expf(m_b - mnb);
        m_a = mna; m_b = mnb;

        // exp -> fp16 P A-fragments; l sums the ROUNDED values for consistency.
        uint32_t phi[4][4];
        float rs_a = 0.f, rs_b = 0.f;
#pragma unroll
        for (int ks = 0; ks < 4; ks++) {
#pragma unroll
            for (int jj = 0; jj < 2; jj++) {
                const int nf = 2*ks + jj;
                float p0 = __expf(sacc[nf][0] - m_a);
                float p1 = __expf(sacc[nf][1] - m_a);
                float p2 = __expf(sacc[nf][2] - m_b);
                float p3 = __expf(sacc[nf][3] - m_b);
                float h0f = __half2float(__float2half_rn(p0));
                float h1f = __half2float(__float2half_rn(p1));
                float h2f = __half2float(__float2half_rn(p2));
                float h3f = __half2float(__float2half_rn(p3));
                rs_a += h0f + h1f;
                rs_b += h2f + h3f;
                phi[ks][2*jj + 0] = pack_h2(h0f, h1f);
                phi[ks][2*jj + 1] = pack_h2(h2f, h3f);
            }
        }
        rs_a += __shfl_xor_sync(0xffffffffu, rs_a, 1);
        rs_a += __shfl_xor_sync(0xffffffffu, rs_a, 2);
        rs_b += __shfl_xor_sync(0xffffffffu, rs_b, 1);
        rs_b += __shfl_xor_sync(0xffffffffu, rs_b, 2);
        l_a = l_a * ala + rs_a;
        l_b = l_b * alb + rs_b;
#pragma unroll
        for (int nf = 0; nf < 8; nf++) {
            oacc[nf][0] *= ala; oacc[nf][1] *= ala;
            oacc[nf][2] *= alb; oacc[nf][3] *= alb;
        }

        // ---- O += P V (1-pass; x4 V fragments) ----
#pragma unroll
        for (int ks = 0; ks < 4; ks++) {
#pragma unroll
            for (int np = 0; np < 4; np++) {
                const int nf0 = 2*np, nf1 = 2*np + 1;
                uint32_t va = st + (uint32_t)((np*16 + rb) * ASTR) + kb + ks*32;
                uint32_t v4[4];
                ldsm_x4(v4, va + AVS);
                mma16816(oacc[nf0], phi[ks], v4);
                mma16816(oacc[nf1], phi[ks], v4 + 2);
            }
        }
    }

    // ---- epilogue: normalize, emit Hc single fp16 ----
    const float iva = 1.0f / l_a, ivb = 1.0f / l_b;
    const int b = bh >> 4, h = bh & 15;
    const int tok_a = qblk*128 + wid*16 + g;
    const int tok_b = tok_a + 8;
#pragma unroll
    for (int nf = 0; nf < 8; nf++) {
        const int d = h*HD + nf*8 + 2*tg;
        float v0 = oacc[nf][0]*iva, v1 = oacc[nf][1]*iva;
        float v2 = oacc[nf][2]*ivb, v3 = oacc[nf][3]*ivb;
        size_t oa = ((size_t)(b*SEQ + tok_a))*EMB + d;
        size_t ob = ((size_t)(b*SEQ + tok_b))*EMB + d;
        *(__half2*)(g_Hc + oa) =
            __halves2half2(__float2half_rn(v0), __float2half_rn(v1));
        *(__half2*)(g_Hc + ob) =
            __halves2half2(__float2half_rn(v2), __float2half_rn(v3));
    }
}

// ---------------------------------------------------------------------------
extern "C" void kernel_launch(void* const* d_in, const int* in_sizes, int n_in,
                              void* d_out, int out_size)
{
    (void)in_sizes; (void)n_in; (void)out_size;
    const float* x  = (const float*)d_in[0];
    const float* Wq = (const float*)d_in[1];
    const float* bq = (const float*)d_in[2];
    const float* Wk = (const float*)d_in[3];
    const float* bk = (const float*)d_in[4];
    const float* Wv = (const float*)d_in[5];
    const float* bv = (const float*)d_in[6];
    const float* Wo = (const float*)d_in[7];
    const float* bo = (const float*)d_in[8];
    float* out = (float*)d_out;

    cudaFuncSetAttribute(qkv_gemm_tc,
                         cudaFuncAttributeMaxDynamicSharedMemorySize,
                         GEMM_SMEM_BYTES);
    cudaFuncSetAttribute(out_gemm_tc,
                         cudaFuncAttributeMaxDynamicSharedMemorySize,
                         GEMM_SMEM_BYTES);
    cudaFuncSetAttribute(attn_mma,
                         cudaFuncAttributeMaxDynamicSharedMemorySize,
                         ATT_SMEM);

    split_kernel<<<dim3(128, 1, 5), 256>>>(x, Wq, Wk, Wv, Wo);
    qkv_gemm_tc<<<dim3(MTOT/128, EMB/128, 3), 256, GEMM_SMEM_BYTES>>>(bq, bk, bv);
    attn_mma<<<dim3(SEQ/128, BHTOT), 256, ATT_SMEM>>>();
    out_gemm_tc<<<dim3(MTOT/128, EMB/128), 256, GEMM_SMEM_BYTES>>>(bo, out);
}